// round 7
// baseline (speedup 1.0000x reference)
#include <cuda_runtime.h>
#include <math.h>

// Problem constants
#define SEQ   4096
#define HID   2048
#define RNK   1024
#define NHEAD 16
#define DHEAD 128

// Scratch (device globals: allocation-free per harness rules)
__device__ float g_T[3 * SEQ * RNK];     // low-rank intermediates  (48 MB)
__device__ float g_QKV[3 * SEQ * HID];   // Q, K, V                 (96 MB)
__device__ float g_AO[SEQ * HID];        // attention output        (32 MB)

// ---------------------------------------------------------------------------
// SGEMM (NT): C[M,N] = A[M,K] * B[N,K]^T (+ bias[N]).  All dims % 128 == 0,
// K % 16 == 0.  128x128 tile, BK=16, 256 threads, 8x8 per-thread fragment.
// ---------------------------------------------------------------------------
__global__ __launch_bounds__(256)
void sgemm_nt(const float* __restrict__ A, const float* __restrict__ B,
              float* __restrict__ C, const float* __restrict__ bias,
              int M, int N, int K)
{
    __shared__ float As[16][128];
    __shared__ float Bs[16][128];

    const int tid = threadIdx.x;
    const int m0 = blockIdx.y * 128;
    const int n0 = blockIdx.x * 128;
    const int tx = tid & 15;          // 16 col-groups of 8
    const int ty = tid >> 4;          // 16 row-groups of 8
    const int lrow = tid >> 2;        // 0..63 loader row
    const int lcol = (tid & 3) << 2;  // 0,4,8,12 loader col

    float acc[8][8];
#pragma unroll
    for (int i = 0; i < 8; i++)
#pragma unroll
        for (int j = 0; j < 8; j++) acc[i][j] = 0.0f;

    for (int k0 = 0; k0 < K; k0 += 16) {
#pragma unroll
        for (int h = 0; h < 2; h++) {
            const int row = lrow + h * 64;
            float4 va = *(const float4*)(A + (size_t)(m0 + row) * K + k0 + lcol);
            As[lcol + 0][row] = va.x; As[lcol + 1][row] = va.y;
            As[lcol + 2][row] = va.z; As[lcol + 3][row] = va.w;
            float4 vb = *(const float4*)(B + (size_t)(n0 + row) * K + k0 + lcol);
            Bs[lcol + 0][row] = vb.x; Bs[lcol + 1][row] = vb.y;
            Bs[lcol + 2][row] = vb.z; Bs[lcol + 3][row] = vb.w;
        }
        __syncthreads();

#pragma unroll
        for (int kk = 0; kk < 16; kk++) {
            float a[8], b[8];
            *(float4*)&a[0] = *(const float4*)&As[kk][ty * 8];
            *(float4*)&a[4] = *(const float4*)&As[kk][ty * 8 + 4];
            *(float4*)&b[0] = *(const float4*)&Bs[kk][tx * 8];
            *(float4*)&b[4] = *(const float4*)&Bs[kk][tx * 8 + 4];
#pragma unroll
            for (int i = 0; i < 8; i++)
#pragma unroll
                for (int j = 0; j < 8; j++)
                    acc[i][j] = fmaf(a[i], b[j], acc[i][j]);
        }
        __syncthreads();
    }

    float bb[8];
#pragma unroll
    for (int j = 0; j < 8; j++)
        bb[j] = bias ? bias[n0 + tx * 8 + j] : 0.0f;

#pragma unroll
    for (int i = 0; i < 8; i++) {
        const int m = m0 + ty * 8 + i;
        float4 o0 = make_float4(acc[i][0] + bb[0], acc[i][1] + bb[1],
                                acc[i][2] + bb[2], acc[i][3] + bb[3]);
        float4 o1 = make_float4(acc[i][4] + bb[4], acc[i][5] + bb[5],
                                acc[i][6] + bb[6], acc[i][7] + bb[7]);
        *(float4*)(C + (size_t)m * N + n0 + tx * 8)     = o0;
        *(float4*)(C + (size_t)m * N + n0 + tx * 8 + 4) = o1;
    }
}

// ---------------------------------------------------------------------------
// Flash attention (fp32, online softmax).  One block = one head x 64 queries.
// KV tiles of 64 keys.  256 threads: thread (ty,tx) owns 4 query rows
// (ty*4+i) and, for S, 4 key cols (tx*4+j); for O, 8 d-cols (tx*8+jj).
// Row reductions via shfl across the 16 tx lanes (xor<=8 stays in-half).
// ---------------------------------------------------------------------------
#define QS_STRIDE 132   // pad to dodge bank conflicts on column-wise reads
#define ATT_SMEM_FLOATS (64 * QS_STRIDE * 2 + 64 * 128 + 64 * 64)
#define ATT_SMEM_BYTES  (ATT_SMEM_FLOATS * 4)

__global__ __launch_bounds__(256)
void flash_attn(const float* __restrict__ Qg, const float* __restrict__ Kg,
                const float* __restrict__ Vg, const float* __restrict__ mask,
                float* __restrict__ Og)
{
    extern __shared__ float sm[];
    float* Qs = sm;                        // [64][132]
    float* Ks = Qs + 64 * QS_STRIDE;       // [64][132]
    float* Vs = Ks + 64 * QS_STRIDE;       // [64][128]
    float* Ps = Vs + 64 * 128;             // [64][64]

    const int tid = threadIdx.x;
    const int tx = tid & 15;
    const int ty = tid >> 4;
    const int h = blockIdx.y;
    const int q0 = blockIdx.x * 64;
    const int hoff = h * DHEAD;
    const float scale = 0.08838834764831845f;  // 1/sqrt(128)

    // Load Q tile (64 x 128)
#pragma unroll
    for (int t = 0; t < 8; t++) {
        const int idx = tid + t * 256;
        const int row = idx >> 5;
        const int c4 = (idx & 31) << 2;
        *(float4*)&Qs[row * QS_STRIDE + c4] =
            *(const float4*)&Qg[(size_t)(q0 + row) * HID + hoff + c4];
    }

    float m_i[4], l_i[4], o[4][8];
#pragma unroll
    for (int i = 0; i < 4; i++) {
        m_i[i] = -INFINITY;
        l_i[i] = 0.0f;
#pragma unroll
        for (int jj = 0; jj < 8; jj++) o[i][jj] = 0.0f;
    }

    for (int j0 = 0; j0 < SEQ; j0 += 64) {
        __syncthreads();   // previous iteration's smem reads complete
        // Load K,V tiles
#pragma unroll
        for (int t = 0; t < 8; t++) {
            const int idx = tid + t * 256;
            const int row = idx >> 5;
            const int c4 = (idx & 31) << 2;
            *(float4*)&Ks[row * QS_STRIDE + c4] =
                *(const float4*)&Kg[(size_t)(j0 + row) * HID + hoff + c4];
            *(float4*)&Vs[row * 128 + c4] =
                *(const float4*)&Vg[(size_t)(j0 + row) * HID + hoff + c4];
        }
        __syncthreads();

        // S = Q K^T  (4x4 fragment per thread)
        float s[4][4];
#pragma unroll
        for (int i = 0; i < 4; i++)
#pragma unroll
            for (int j = 0; j < 4; j++) s[i][j] = 0.0f;

#pragma unroll 4
        for (int d0 = 0; d0 < 128; d0 += 4) {
            float4 a[4], b[4];
#pragma unroll
            for (int i = 0; i < 4; i++)
                a[i] = *(const float4*)&Qs[(ty * 4 + i) * QS_STRIDE + d0];
#pragma unroll
            for (int j = 0; j < 4; j++)
                b[j] = *(const float4*)&Ks[(tx * 4 + j) * QS_STRIDE + d0];
#pragma unroll
            for (int i = 0; i < 4; i++)
#pragma unroll
                for (int j = 0; j < 4; j++) {
                    s[i][j] = fmaf(a[i].x, b[j].x, s[i][j]);
                    s[i][j] = fmaf(a[i].y, b[j].y, s[i][j]);
                    s[i][j] = fmaf(a[i].z, b[j].z, s[i][j]);
                    s[i][j] = fmaf(a[i].w, b[j].w, s[i][j]);
                }
        }

        // scale + additive mask
#pragma unroll
        for (int i = 0; i < 4; i++) {
            float4 mk = *(const float4*)&mask[(size_t)(q0 + ty * 4 + i) * SEQ + j0 + tx * 4];
            s[i][0] = s[i][0] * scale + mk.x;
            s[i][1] = s[i][1] * scale + mk.y;
            s[i][2] = s[i][2] * scale + mk.z;
            s[i][3] = s[i][3] * scale + mk.w;
        }

        // Online softmax, write P to shared
#pragma unroll
        for (int i = 0; i < 4; i++) {
            float mx = fmaxf(fmaxf(s[i][0], s[i][1]), fmaxf(s[i][2], s[i][3]));
#pragma unroll
            for (int w = 1; w <= 8; w <<= 1)
                mx = fmaxf(mx, __shfl_xor_sync(0xffffffffu, mx, w));
            const float m_new = fmaxf(m_i[i], mx);
            const float alpha = __expf(m_i[i] - m_new);
            float p0 = __expf(s[i][0] - m_new);
            float p1 = __expf(s[i][1] - m_new);
            float p2 = __expf(s[i][2] - m_new);
            float p3 = __expf(s[i][3] - m_new);
            float rs = p0 + p1 + p2 + p3;
#pragma unroll
            for (int w = 1; w <= 8; w <<= 1)
                rs += __shfl_xor_sync(0xffffffffu, rs, w);
            l_i[i] = l_i[i] * alpha + rs;
            m_i[i] = m_new;
#pragma unroll
            for (int jj = 0; jj < 8; jj++) o[i][jj] *= alpha;
            *(float4*)&Ps[(ty * 4 + i) * 64 + tx * 4] = make_float4(p0, p1, p2, p3);
        }
        __syncthreads();   // Ps visible

        // O += P @ V
#pragma unroll 4
        for (int k = 0; k < 64; k++) {
            float4 v0 = *(const float4*)&Vs[k * 128 + tx * 8];
            float4 v1 = *(const float4*)&Vs[k * 128 + tx * 8 + 4];
#pragma unroll
            for (int i = 0; i < 4; i++) {
                const float p = Ps[(ty * 4 + i) * 64 + k];
                o[i][0] = fmaf(p, v0.x, o[i][0]);
                o[i][1] = fmaf(p, v0.y, o[i][1]);
                o[i][2] = fmaf(p, v0.z, o[i][2]);
                o[i][3] = fmaf(p, v0.w, o[i][3]);
                o[i][4] = fmaf(p, v1.x, o[i][4]);
                o[i][5] = fmaf(p, v1.y, o[i][5]);
                o[i][6] = fmaf(p, v1.z, o[i][6]);
                o[i][7] = fmaf(p, v1.w, o[i][7]);
            }
        }
    }

    // Normalize and write (merge heads: out[q, h*128 + d])
#pragma unroll
    for (int i = 0; i < 4; i++) {
        const float inv = 1.0f / l_i[i];
        float4 w0 = make_float4(o[i][0] * inv, o[i][1] * inv, o[i][2] * inv, o[i][3] * inv);
        float4 w1 = make_float4(o[i][4] * inv, o[i][5] * inv, o[i][6] * inv, o[i][7] * inv);
        float* dst = Og + (size_t)(q0 + ty * 4 + i) * HID + hoff + tx * 8;
        *(float4*)dst = w0;
        *(float4*)(dst + 4) = w1;
    }
}

// ---------------------------------------------------------------------------
// Launch: 3x (x @ V^T) -> 3x (t @ U^T) -> flash attention -> (o @ W^T + b)
// ---------------------------------------------------------------------------
extern "C" void kernel_launch(void* const* d_in, const int* in_sizes, int n_in,
                              void* d_out, int out_size)
{
    (void)in_sizes; (void)n_in; (void)out_size;
    const float* x    = (const float*)d_in[0];
    const float* mask = (const float*)d_in[1];
    const float* Vw[3] = { (const float*)d_in[2], (const float*)d_in[4], (const float*)d_in[6] };
    const float* Uw[3] = { (const float*)d_in[3], (const float*)d_in[5], (const float*)d_in[7] };
    const float* oW = (const float*)d_in[8];
    const float* ob = (const float*)d_in[9];
    float* out = (float*)d_out;

    void *pT, *pQKV, *pAO;
    cudaGetSymbolAddress(&pT, g_T);
    cudaGetSymbolAddress(&pQKV, g_QKV);
    cudaGetSymbolAddress(&pAO, g_AO);
    float* T   = (float*)pT;
    float* QKV = (float*)pQKV;
    float* AO  = (float*)pAO;

    cudaFuncSetAttribute(flash_attn, cudaFuncAttributeMaxDynamicSharedMemorySize,
                         ATT_SMEM_BYTES);

    // Stage 1: T_i = X @ V_i^T      [4096,2048] x [1024,2048]^T -> [4096,1024]
    {
        dim3 grid(RNK / 128, SEQ / 128);
        for (int i = 0; i < 3; i++)
            sgemm_nt<<<grid, 256>>>(x, Vw[i], T + (size_t)i * SEQ * RNK, nullptr,
                                    SEQ, RNK, HID);
    }
    // Stage 2: QKV_i = T_i @ U_i^T  [4096,1024] x [2048,1024]^T -> [4096,2048]
    {
        dim3 grid(HID / 128, SEQ / 128);
        for (int i = 0; i < 3; i++)
            sgemm_nt<<<grid, 256>>>(T + (size_t)i * SEQ * RNK, Uw[i],
                                    QKV + (size_t)i * SEQ * HID, nullptr,
                                    SEQ, HID, RNK);
    }
    // Stage 3: attention per head
    {
        dim3 grid(SEQ / 64, NHEAD);
        flash_attn<<<grid, 256, ATT_SMEM_BYTES>>>(
            QKV, QKV + (size_t)SEQ * HID, QKV + (size_t)2 * SEQ * HID, mask, AO);
    }
    // Stage 4: out = AO @ oW^T + ob
    {
        dim3 grid(HID / 128, SEQ / 128);
        sgemm_nt<<<grid, 256>>>(AO, oW, out, ob, SEQ, HID, HID);
    }
}

// round 8
// speedup vs baseline: 1.0001x; 1.0001x over previous
#include <cuda_runtime.h>
#include <math.h>

// Problem constants
#define SEQ   4096
#define HID   2048
#define RNK   1024
#define NHEAD 16
#define DHEAD 128

// Scratch (device globals: allocation-free per harness rules)
__device__ float g_T[3 * SEQ * RNK];     // low-rank intermediates  (48 MB)
__device__ float g_QKV[3 * SEQ * HID];   // Q, K, V                 (96 MB)
__device__ float g_AO[SEQ * HID];        // attention output        (32 MB)

// ---------------------------------------------------------------------------
// SGEMM (NT): C[M,N] = A[M,K] * B[N,K]^T (+ bias[N]).  All dims % 128 == 0,
// K % 16 == 0.  128x128 tile, BK=16, 256 threads, 8x8 per-thread fragment.
// ---------------------------------------------------------------------------
__global__ __launch_bounds__(256)
void sgemm_nt(const float* __restrict__ A, const float* __restrict__ B,
              float* __restrict__ C, const float* __restrict__ bias,
              int M, int N, int K)
{
    __shared__ float As[16][128];
    __shared__ float Bs[16][128];

    const int tid = threadIdx.x;
    const int m0 = blockIdx.y * 128;
    const int n0 = blockIdx.x * 128;
    const int tx = tid & 15;          // 16 col-groups of 8
    const int ty = tid >> 4;          // 16 row-groups of 8
    const int lrow = tid >> 2;        // 0..63 loader row
    const int lcol = (tid & 3) << 2;  // 0,4,8,12 loader col

    float acc[8][8];
#pragma unroll
    for (int i = 0; i < 8; i++)
#pragma unroll
        for (int j = 0; j < 8; j++) acc[i][j] = 0.0f;

    for (int k0 = 0; k0 < K; k0 += 16) {
#pragma unroll
        for (int h = 0; h < 2; h++) {
            const int row = lrow + h * 64;
            float4 va = *(const float4*)(A + (size_t)(m0 + row) * K + k0 + lcol);
            As[lcol + 0][row] = va.x; As[lcol + 1][row] = va.y;
            As[lcol + 2][row] = va.z; As[lcol + 3][row] = va.w;
            float4 vb = *(const float4*)(B + (size_t)(n0 + row) * K + k0 + lcol);
            Bs[lcol + 0][row] = vb.x; Bs[lcol + 1][row] = vb.y;
            Bs[lcol + 2][row] = vb.z; Bs[lcol + 3][row] = vb.w;
        }
        __syncthreads();

#pragma unroll
        for (int kk = 0; kk < 16; kk++) {
            float a[8], b[8];
            *(float4*)&a[0] = *(const float4*)&As[kk][ty * 8];
            *(float4*)&a[4] = *(const float4*)&As[kk][ty * 8 + 4];
            *(float4*)&b[0] = *(const float4*)&Bs[kk][tx * 8];
            *(float4*)&b[4] = *(const float4*)&Bs[kk][tx * 8 + 4];
#pragma unroll
            for (int i = 0; i < 8; i++)
#pragma unroll
                for (int j = 0; j < 8; j++)
                    acc[i][j] = fmaf(a[i], b[j], acc[i][j]);
        }
        __syncthreads();
    }

    float bb[8];
#pragma unroll
    for (int j = 0; j < 8; j++)
        bb[j] = bias ? bias[n0 + tx * 8 + j] : 0.0f;

#pragma unroll
    for (int i = 0; i < 8; i++) {
        const int m = m0 + ty * 8 + i;
        float4 o0 = make_float4(acc[i][0] + bb[0], acc[i][1] + bb[1],
                                acc[i][2] + bb[2], acc[i][3] + bb[3]);
        float4 o1 = make_float4(acc[i][4] + bb[4], acc[i][5] + bb[5],
                                acc[i][6] + bb[6], acc[i][7] + bb[7]);
        *(float4*)(C + (size_t)m * N + n0 + tx * 8)     = o0;
        *(float4*)(C + (size_t)m * N + n0 + tx * 8 + 4) = o1;
    }
}

// ---------------------------------------------------------------------------
// Flash attention (fp32, online softmax).  One block = one head x 64 queries.
// KV tiles of 64 keys.  256 threads: thread (ty,tx) owns 4 query rows
// (ty*4+i) and, for S, 4 key cols (tx*4+j); for O, 8 d-cols (tx*8+jj).
// Row reductions via shfl across the 16 tx lanes (xor<=8 stays in-half).
// ---------------------------------------------------------------------------
#define QS_STRIDE 132   // pad to dodge bank conflicts on column-wise reads
#define ATT_SMEM_FLOATS (64 * QS_STRIDE * 2 + 64 * 128 + 64 * 64)
#define ATT_SMEM_BYTES  (ATT_SMEM_FLOATS * 4)

__global__ __launch_bounds__(256)
void flash_attn(const float* __restrict__ Qg, const float* __restrict__ Kg,
                const float* __restrict__ Vg, const float* __restrict__ mask,
                float* __restrict__ Og)
{
    extern __shared__ float sm[];
    float* Qs = sm;                        // [64][132]
    float* Ks = Qs + 64 * QS_STRIDE;       // [64][132]
    float* Vs = Ks + 64 * QS_STRIDE;       // [64][128]
    float* Ps = Vs + 64 * 128;             // [64][64]

    const int tid = threadIdx.x;
    const int tx = tid & 15;
    const int ty = tid >> 4;
    const int h = blockIdx.y;
    const int q0 = blockIdx.x * 64;
    const int hoff = h * DHEAD;
    const float scale = 0.08838834764831845f;  // 1/sqrt(128)

    // Load Q tile (64 x 128)
#pragma unroll
    for (int t = 0; t < 8; t++) {
        const int idx = tid + t * 256;
        const int row = idx >> 5;
        const int c4 = (idx & 31) << 2;
        *(float4*)&Qs[row * QS_STRIDE + c4] =
            *(const float4*)&Qg[(size_t)(q0 + row) * HID + hoff + c4];
    }

    float m_i[4], l_i[4], o[4][8];
#pragma unroll
    for (int i = 0; i < 4; i++) {
        m_i[i] = -INFINITY;
        l_i[i] = 0.0f;
#pragma unroll
        for (int jj = 0; jj < 8; jj++) o[i][jj] = 0.0f;
    }

    for (int j0 = 0; j0 < SEQ; j0 += 64) {
        __syncthreads();   // previous iteration's smem reads complete
        // Load K,V tiles
#pragma unroll
        for (int t = 0; t < 8; t++) {
            const int idx = tid + t * 256;
            const int row = idx >> 5;
            const int c4 = (idx & 31) << 2;
            *(float4*)&Ks[row * QS_STRIDE + c4] =
                *(const float4*)&Kg[(size_t)(j0 + row) * HID + hoff + c4];
            *(float4*)&Vs[row * 128 + c4] =
                *(const float4*)&Vg[(size_t)(j0 + row) * HID + hoff + c4];
        }
        __syncthreads();

        // S = Q K^T  (4x4 fragment per thread)
        float s[4][4];
#pragma unroll
        for (int i = 0; i < 4; i++)
#pragma unroll
            for (int j = 0; j < 4; j++) s[i][j] = 0.0f;

#pragma unroll 4
        for (int d0 = 0; d0 < 128; d0 += 4) {
            float4 a[4], b[4];
#pragma unroll
            for (int i = 0; i < 4; i++)
                a[i] = *(const float4*)&Qs[(ty * 4 + i) * QS_STRIDE + d0];
#pragma unroll
            for (int j = 0; j < 4; j++)
                b[j] = *(const float4*)&Ks[(tx * 4 + j) * QS_STRIDE + d0];
#pragma unroll
            for (int i = 0; i < 4; i++)
#pragma unroll
                for (int j = 0; j < 4; j++) {
                    s[i][j] = fmaf(a[i].x, b[j].x, s[i][j]);
                    s[i][j] = fmaf(a[i].y, b[j].y, s[i][j]);
                    s[i][j] = fmaf(a[i].z, b[j].z, s[i][j]);
                    s[i][j] = fmaf(a[i].w, b[j].w, s[i][j]);
                }
        }

        // scale + additive mask
#pragma unroll
        for (int i = 0; i < 4; i++) {
            float4 mk = *(const float4*)&mask[(size_t)(q0 + ty * 4 + i) * SEQ + j0 + tx * 4];
            s[i][0] = s[i][0] * scale + mk.x;
            s[i][1] = s[i][1] * scale + mk.y;
            s[i][2] = s[i][2] * scale + mk.z;
            s[i][3] = s[i][3] * scale + mk.w;
        }

        // Online softmax, write P to shared
#pragma unroll
        for (int i = 0; i < 4; i++) {
            float mx = fmaxf(fmaxf(s[i][0], s[i][1]), fmaxf(s[i][2], s[i][3]));
#pragma unroll
            for (int w = 1; w <= 8; w <<= 1)
                mx = fmaxf(mx, __shfl_xor_sync(0xffffffffu, mx, w));
            const float m_new = fmaxf(m_i[i], mx);
            const float alpha = __expf(m_i[i] - m_new);
            float p0 = __expf(s[i][0] - m_new);
            float p1 = __expf(s[i][1] - m_new);
            float p2 = __expf(s[i][2] - m_new);
            float p3 = __expf(s[i][3] - m_new);
            float rs = p0 + p1 + p2 + p3;
#pragma unroll
            for (int w = 1; w <= 8; w <<= 1)
                rs += __shfl_xor_sync(0xffffffffu, rs, w);
            l_i[i] = l_i[i] * alpha + rs;
            m_i[i] = m_new;
#pragma unroll
            for (int jj = 0; jj < 8; jj++) o[i][jj] *= alpha;
            *(float4*)&Ps[(ty * 4 + i) * 64 + tx * 4] = make_float4(p0, p1, p2, p3);
        }
        __syncthreads();   // Ps visible

        // O += P @ V
#pragma unroll 4
        for (int k = 0; k < 64; k++) {
            float4 v0 = *(const float4*)&Vs[k * 128 + tx * 8];
            float4 v1 = *(const float4*)&Vs[k * 128 + tx * 8 + 4];
#pragma unroll
            for (int i = 0; i < 4; i++) {
                const float p = Ps[(ty * 4 + i) * 64 + k];
                o[i][0] = fmaf(p, v0.x, o[i][0]);
                o[i][1] = fmaf(p, v0.y, o[i][1]);
                o[i][2] = fmaf(p, v0.z, o[i][2]);
                o[i][3] = fmaf(p, v0.w, o[i][3]);
                o[i][4] = fmaf(p, v1.x, o[i][4]);
                o[i][5] = fmaf(p, v1.y, o[i][5]);
                o[i][6] = fmaf(p, v1.z, o[i][6]);
                o[i][7] = fmaf(p, v1.w, o[i][7]);
            }
        }
    }

    // Normalize and write (merge heads: out[q, h*128 + d])
#pragma unroll
    for (int i = 0; i < 4; i++) {
        const float inv = 1.0f / l_i[i];
        float4 w0 = make_float4(o[i][0] * inv, o[i][1] * inv, o[i][2] * inv, o[i][3] * inv);
        float4 w1 = make_float4(o[i][4] * inv, o[i][5] * inv, o[i][6] * inv, o[i][7] * inv);
        float* dst = Og + (size_t)(q0 + ty * 4 + i) * HID + hoff + tx * 8;
        *(float4*)dst = w0;
        *(float4*)(dst + 4) = w1;
    }
}

// ---------------------------------------------------------------------------
// Launch: 3x (x @ V^T) -> 3x (t @ U^T) -> flash attention -> (o @ W^T + b)
// ---------------------------------------------------------------------------
extern "C" void kernel_launch(void* const* d_in, const int* in_sizes, int n_in,
                              void* d_out, int out_size)
{
    (void)in_sizes; (void)n_in; (void)out_size;
    const float* x    = (const float*)d_in[0];
    const float* mask = (const float*)d_in[1];
    const float* Vw[3] = { (const float*)d_in[2], (const float*)d_in[4], (const float*)d_in[6] };
    const float* Uw[3] = { (const float*)d_in[3], (const float*)d_in[5], (const float*)d_in[7] };
    const float* oW = (const float*)d_in[8];
    const float* ob = (const float*)d_in[9];
    float* out = (float*)d_out;

    void *pT, *pQKV, *pAO;
    cudaGetSymbolAddress(&pT, g_T);
    cudaGetSymbolAddress(&pQKV, g_QKV);
    cudaGetSymbolAddress(&pAO, g_AO);
    float* T   = (float*)pT;
    float* QKV = (float*)pQKV;
    float* AO  = (float*)pAO;

    cudaFuncSetAttribute(flash_attn, cudaFuncAttributeMaxDynamicSharedMemorySize,
                         ATT_SMEM_BYTES);

    // Stage 1: T_i = X @ V_i^T      [4096,2048] x [1024,2048]^T -> [4096,1024]
    {
        dim3 grid(RNK / 128, SEQ / 128);
        for (int i = 0; i < 3; i++)
            sgemm_nt<<<grid, 256>>>(x, Vw[i], T + (size_t)i * SEQ * RNK, nullptr,
                                    SEQ, RNK, HID);
    }
    // Stage 2: QKV_i = T_i @ U_i^T  [4096,1024] x [2048,1024]^T -> [4096,2048]
    {
        dim3 grid(HID / 128, SEQ / 128);
        for (int i = 0; i < 3; i++)
            sgemm_nt<<<grid, 256>>>(T + (size_t)i * SEQ * RNK, Uw[i],
                                    QKV + (size_t)i * SEQ * HID, nullptr,
                                    SEQ, HID, RNK);
    }
    // Stage 3: attention per head
    {
        dim3 grid(SEQ / 64, NHEAD);
        flash_attn<<<grid, 256, ATT_SMEM_BYTES>>>(
            QKV, QKV + (size_t)SEQ * HID, QKV + (size_t)2 * SEQ * HID, mask, AO);
    }
    // Stage 4: out = AO @ oW^T + ob
    {
        dim3 grid(HID / 128, SEQ / 128);
        sgemm_nt<<<grid, 256>>>(AO, oW, out, ob, SEQ, HID, HID);
    }
}

// round 10
// speedup vs baseline: 1.2916x; 1.2914x over previous
#include <cuda_runtime.h>
#include <math.h>
#include <stdint.h>

// Problem constants
#define SEQ   4096
#define HID   2048
#define RNK   1024
#define NHEAD 16
#define DHEAD 128

// Scratch (device globals: allocation-free per harness rules)
__device__ float g_T[3 * SEQ * RNK];     // low-rank intermediates  (48 MB)
__device__ float g_QKV[3 * SEQ * HID];   // Q, K, V                 (96 MB)
__device__ float g_AO[SEQ * HID];        // attention output        (32 MB)

// ===========================================================================
// TF32 tensor-core GEMM (NT): C[M,N] = A[M,K] * B[N,K]^T (+ bias[N]).
// Tile 128x128x32, 256 threads (8 warps, 4x2 warp grid), warp tile 32x64,
// mma.sync.m16n8k8.tf32 fragments (2 m-tiles x 8 n-tiles per warp).
// Smem layout [row][k] with k-stride padded to 36 floats:
//   - fragment LDS.32 banks = gid*4 + tig + kb  -> 32 distinct (conflict-free)
//   - loader STS.128 phases sweep all 32 banks  -> conflict-free
//   - LDG float4 fully coalesced (8 lanes cover one 128B row segment)
// ===========================================================================
#define BM 128
#define BN 128
#define BK 32
#define KST 36   // padded k-stride (36 mod 32 == 4)

__device__ __forceinline__ uint32_t f2tf(float x) {
    uint32_t r;
    asm("cvt.rna.tf32.f32 %0, %1;" : "=r"(r) : "f"(x));
    return r;
}

__device__ __forceinline__ void mma_tf32(float* d, const uint32_t* a, const uint32_t* b) {
    asm volatile(
        "mma.sync.aligned.m16n8k8.row.col.f32.tf32.tf32.f32 "
        "{%0,%1,%2,%3}, {%4,%5,%6,%7}, {%8,%9}, {%0,%1,%2,%3};\n"
        : "+f"(d[0]), "+f"(d[1]), "+f"(d[2]), "+f"(d[3])
        : "r"(a[0]), "r"(a[1]), "r"(a[2]), "r"(a[3]),
          "r"(b[0]), "r"(b[1]));
}

__global__ __launch_bounds__(256, 2)
void gemm_tf32_nt(const float* __restrict__ A, const float* __restrict__ B,
                  float* __restrict__ C, const float* __restrict__ bias,
                  int M, int N, int K)
{
    __shared__ uint32_t As[BM * KST];   // [m][k] tf32 bit patterns
    __shared__ uint32_t Bs[BN * KST];   // [n][k]

    const int tid  = threadIdx.x;
    const int lane = tid & 31;
    const int warp = tid >> 5;
    const int gid  = lane >> 2;   // 0..7
    const int tig  = lane & 3;    // 0..3
    const int wm   = warp & 3;    // 4 warp rows of 32
    const int wn   = warp >> 2;   // 2 warp cols of 64
    const int m0   = blockIdx.y * BM;
    const int n0   = blockIdx.x * BN;

    float acc[2][8][4];
#pragma unroll
    for (int mt = 0; mt < 2; mt++)
#pragma unroll
        for (int nt = 0; nt < 8; nt++)
#pragma unroll
            for (int r = 0; r < 4; r++) acc[mt][nt][r] = 0.0f;

    for (int k0 = 0; k0 < K; k0 += BK) {
        __syncthreads();   // previous k-step's smem reads complete
        // Load A/B tiles (128x32 each), convert to tf32, store [row][k]
#pragma unroll
        for (int it = 0; it < 4; it++) {
            const int idx = tid + it * 256;           // 0..1023
            const int m  = idx >> 3;                  // 0..127
            const int kq = (idx & 7) << 2;            // 0,4,...,28
            float4 va = *(const float4*)(A + (size_t)(m0 + m) * K + k0 + kq);
            uint4 ua = make_uint4(f2tf(va.x), f2tf(va.y), f2tf(va.z), f2tf(va.w));
            *(uint4*)&As[m * KST + kq] = ua;
            float4 vb = *(const float4*)(B + (size_t)(n0 + m) * K + k0 + kq);
            uint4 ub = make_uint4(f2tf(vb.x), f2tf(vb.y), f2tf(vb.z), f2tf(vb.w));
            *(uint4*)&Bs[m * KST + kq] = ub;
        }
        __syncthreads();

#pragma unroll
        for (int kb = 0; kb < BK; kb += 8) {
            uint32_t a[2][4], b[8][2];
#pragma unroll
            for (int mt = 0; mt < 2; mt++) {
                const int r = wm * 32 + mt * 16 + gid;
                a[mt][0] = As[r * KST + kb + tig];
                a[mt][1] = As[(r + 8) * KST + kb + tig];
                a[mt][2] = As[r * KST + kb + tig + 4];
                a[mt][3] = As[(r + 8) * KST + kb + tig + 4];
            }
#pragma unroll
            for (int nt = 0; nt < 8; nt++) {
                const int c = wn * 64 + nt * 8 + gid;
                b[nt][0] = Bs[c * KST + kb + tig];
                b[nt][1] = Bs[c * KST + kb + tig + 4];
            }
#pragma unroll
            for (int mt = 0; mt < 2; mt++)
#pragma unroll
                for (int nt = 0; nt < 8; nt++)
                    mma_tf32(acc[mt][nt], a[mt], b[nt]);
        }
    }

    // Epilogue: c0,c1 at (row, 2*tig(+1)), c2,c3 at (row+8)
#pragma unroll
    for (int mt = 0; mt < 2; mt++) {
        const int row = m0 + wm * 32 + mt * 16 + gid;
#pragma unroll
        for (int nt = 0; nt < 8; nt++) {
            const int col = n0 + wn * 64 + nt * 8 + tig * 2;
            const float b0 = bias ? bias[col] : 0.0f;
            const float b1 = bias ? bias[col + 1] : 0.0f;
            float2 v0 = make_float2(acc[mt][nt][0] + b0, acc[mt][nt][1] + b1);
            float2 v1 = make_float2(acc[mt][nt][2] + b0, acc[mt][nt][3] + b1);
            *(float2*)(C + (size_t)row * N + col)       = v0;
            *(float2*)(C + (size_t)(row + 8) * N + col) = v1;
        }
    }
}

// ---------------------------------------------------------------------------
// Flash attention (fp32, online softmax) — unchanged known-good kernel.
// One block = one head x 64 queries, KV tiles of 64 keys.
// ---------------------------------------------------------------------------
#define QS_STRIDE 132
#define ATT_SMEM_FLOATS (64 * QS_STRIDE * 2 + 64 * 128 + 64 * 64)
#define ATT_SMEM_BYTES  (ATT_SMEM_FLOATS * 4)

__global__ __launch_bounds__(256)
void flash_attn(const float* __restrict__ Qg, const float* __restrict__ Kg,
                const float* __restrict__ Vg, const float* __restrict__ mask,
                float* __restrict__ Og)
{
    extern __shared__ float sm[];
    float* Qs = sm;                        // [64][132]
    float* Ks = Qs + 64 * QS_STRIDE;       // [64][132]
    float* Vs = Ks + 64 * QS_STRIDE;       // [64][128]
    float* Ps = Vs + 64 * 128;             // [64][64]

    const int tid = threadIdx.x;
    const int tx = tid & 15;
    const int ty = tid >> 4;
    const int h = blockIdx.y;
    const int q0 = blockIdx.x * 64;
    const int hoff = h * DHEAD;
    const float scale = 0.08838834764831845f;  // 1/sqrt(128)

#pragma unroll
    for (int t = 0; t < 8; t++) {
        const int idx = tid + t * 256;
        const int row = idx >> 5;
        const int c4 = (idx & 31) << 2;
        *(float4*)&Qs[row * QS_STRIDE + c4] =
            *(const float4*)&Qg[(size_t)(q0 + row) * HID + hoff + c4];
    }

    float m_i[4], l_i[4], o[4][8];
#pragma unroll
    for (int i = 0; i < 4; i++) {
        m_i[i] = -INFINITY;
        l_i[i] = 0.0f;
#pragma unroll
        for (int jj = 0; jj < 8; jj++) o[i][jj] = 0.0f;
    }

    for (int j0 = 0; j0 < SEQ; j0 += 64) {
        __syncthreads();
#pragma unroll
        for (int t = 0; t < 8; t++) {
            const int idx = tid + t * 256;
            const int row = idx >> 5;
            const int c4 = (idx & 31) << 2;
            *(float4*)&Ks[row * QS_STRIDE + c4] =
                *(const float4*)&Kg[(size_t)(j0 + row) * HID + hoff + c4];
            *(float4*)&Vs[row * 128 + c4] =
                *(const float4*)&Vg[(size_t)(j0 + row) * HID + hoff + c4];
        }
        __syncthreads();

        float s[4][4];
#pragma unroll
        for (int i = 0; i < 4; i++)
#pragma unroll
            for (int j = 0; j < 4; j++) s[i][j] = 0.0f;

#pragma unroll 4
        for (int d0 = 0; d0 < 128; d0 += 4) {
            float4 a[4], b[4];
#pragma unroll
            for (int i = 0; i < 4; i++)
                a[i] = *(const float4*)&Qs[(ty * 4 + i) * QS_STRIDE + d0];
#pragma unroll
            for (int j = 0; j < 4; j++)
                b[j] = *(const float4*)&Ks[(tx * 4 + j) * QS_STRIDE + d0];
#pragma unroll
            for (int i = 0; i < 4; i++)
#pragma unroll
                for (int j = 0; j < 4; j++) {
                    s[i][j] = fmaf(a[i].x, b[j].x, s[i][j]);
                    s[i][j] = fmaf(a[i].y, b[j].y, s[i][j]);
                    s[i][j] = fmaf(a[i].z, b[j].z, s[i][j]);
                    s[i][j] = fmaf(a[i].w, b[j].w, s[i][j]);
                }
        }

#pragma unroll
        for (int i = 0; i < 4; i++) {
            float4 mk = *(const float4*)&mask[(size_t)(q0 + ty * 4 + i) * SEQ + j0 + tx * 4];
            s[i][0] = s[i][0] * scale + mk.x;
            s[i][1] = s[i][1] * scale + mk.y;
            s[i][2] = s[i][2] * scale + mk.z;
            s[i][3] = s[i][3] * scale + mk.w;
        }

#pragma unroll
        for (int i = 0; i < 4; i++) {
            float mx = fmaxf(fmaxf(s[i][0], s[i][1]), fmaxf(s[i][2], s[i][3]));
#pragma unroll
            for (int w = 1; w <= 8; w <<= 1)
                mx = fmaxf(mx, __shfl_xor_sync(0xffffffffu, mx, w));
            const float m_new = fmaxf(m_i[i], mx);
            const float alpha = __expf(m_i[i] - m_new);
            float p0 = __expf(s[i][0] - m_new);
            float p1 = __expf(s[i][1] - m_new);
            float p2 = __expf(s[i][2] - m_new);
            float p3 = __expf(s[i][3] - m_new);
            float rs = p0 + p1 + p2 + p3;
#pragma unroll
            for (int w = 1; w <= 8; w <<= 1)
                rs += __shfl_xor_sync(0xffffffffu, rs, w);
            l_i[i] = l_i[i] * alpha + rs;
            m_i[i] = m_new;
#pragma unroll
            for (int jj = 0; jj < 8; jj++) o[i][jj] *= alpha;
            *(float4*)&Ps[(ty * 4 + i) * 64 + tx * 4] = make_float4(p0, p1, p2, p3);
        }
        __syncthreads();

#pragma unroll 4
        for (int k = 0; k < 64; k++) {
            float4 v0 = *(const float4*)&Vs[k * 128 + tx * 8];
            float4 v1 = *(const float4*)&Vs[k * 128 + tx * 8 + 4];
#pragma unroll
            for (int i = 0; i < 4; i++) {
                const float p = Ps[(ty * 4 + i) * 64 + k];
                o[i][0] = fmaf(p, v0.x, o[i][0]);
                o[i][1] = fmaf(p, v0.y, o[i][1]);
                o[i][2] = fmaf(p, v0.z, o[i][2]);
                o[i][3] = fmaf(p, v0.w, o[i][3]);
                o[i][4] = fmaf(p, v1.x, o[i][4]);
                o[i][5] = fmaf(p, v1.y, o[i][5]);
                o[i][6] = fmaf(p, v1.z, o[i][6]);
                o[i][7] = fmaf(p, v1.w, o[i][7]);
            }
        }
    }

#pragma unroll
    for (int i = 0; i < 4; i++) {
        const float inv = 1.0f / l_i[i];
        float4 w0 = make_float4(o[i][0] * inv, o[i][1] * inv, o[i][2] * inv, o[i][3] * inv);
        float4 w1 = make_float4(o[i][4] * inv, o[i][5] * inv, o[i][6] * inv, o[i][7] * inv);
        float* dst = Og + (size_t)(q0 + ty * 4 + i) * HID + hoff + tx * 8;
        *(float4*)dst = w0;
        *(float4*)(dst + 4) = w1;
    }
}

// ---------------------------------------------------------------------------
// Launch: 3x (x @ V^T) -> 3x (t @ U^T) -> flash attention -> (o @ W^T + b)
// ---------------------------------------------------------------------------
extern "C" void kernel_launch(void* const* d_in, const int* in_sizes, int n_in,
                              void* d_out, int out_size)
{
    (void)in_sizes; (void)n_in; (void)out_size;
    const float* x    = (const float*)d_in[0];
    const float* mask = (const float*)d_in[1];
    const float* Vw[3] = { (const float*)d_in[2], (const float*)d_in[4], (const float*)d_in[6] };
    const float* Uw[3] = { (const float*)d_in[3], (const float*)d_in[5], (const float*)d_in[7] };
    const float* oW = (const float*)d_in[8];
    const float* ob = (const float*)d_in[9];
    float* out = (float*)d_out;

    void *pT, *pQKV, *pAO;
    cudaGetSymbolAddress(&pT, g_T);
    cudaGetSymbolAddress(&pQKV, g_QKV);
    cudaGetSymbolAddress(&pAO, g_AO);
    float* T   = (float*)pT;
    float* QKV = (float*)pQKV;
    float* AO  = (float*)pAO;

    cudaFuncSetAttribute(flash_attn, cudaFuncAttributeMaxDynamicSharedMemorySize,
                         ATT_SMEM_BYTES);

    // Stage 1: T_i = X @ V_i^T      [4096,2048] x [1024,2048]^T -> [4096,1024]
    {
        dim3 grid(RNK / BN, SEQ / BM);
        for (int i = 0; i < 3; i++)
            gemm_tf32_nt<<<grid, 256>>>(x, Vw[i], T + (size_t)i * SEQ * RNK, nullptr,
                                        SEQ, RNK, HID);
    }
    // Stage 2: QKV_i = T_i @ U_i^T  [4096,1024] x [2048,1024]^T -> [4096,2048]
    {
        dim3 grid(HID / BN, SEQ / BM);
        for (int i = 0; i < 3; i++)
            gemm_tf32_nt<<<grid, 256>>>(T + (size_t)i * SEQ * RNK, Uw[i],
                                        QKV + (size_t)i * SEQ * HID, nullptr,
                                        SEQ, HID, RNK);
    }
    // Stage 3: attention per head
    {
        dim3 grid(SEQ / 64, NHEAD);
        flash_attn<<<grid, 256, ATT_SMEM_BYTES>>>(
            QKV, QKV + (size_t)SEQ * HID, QKV + (size_t)2 * SEQ * HID, mask, AO);
    }
    // Stage 4: out = AO @ oW^T + ob
    {
        dim3 grid(HID / BN, SEQ / BM);
        gemm_tf32_nt<<<grid, 256>>>(AO, oW, out, ob, SEQ, HID, HID);
    }
}

// round 11
// speedup vs baseline: 4.3252x; 3.3489x over previous
#include <cuda_runtime.h>
#include <math.h>
#include <stdint.h>

// Problem constants
#define SEQ   4096
#define HID   2048
#define RNK   1024
#define NHEAD 16
#define DHEAD 128

// Scratch (device globals: allocation-free per harness rules)
__device__ float g_T[3 * SEQ * RNK];     // low-rank intermediates  (48 MB)
__device__ float g_QKV[3 * SEQ * HID];   // Q, K, V                 (96 MB)
__device__ float g_AO[SEQ * HID];        // attention output        (32 MB)

__device__ __forceinline__ uint32_t f2tf(float x) {
    uint32_t r;
    asm("cvt.rna.tf32.f32 %0, %1;" : "=r"(r) : "f"(x));
    return r;
}

__device__ __forceinline__ void mma_tf32(float* d, const uint32_t* a, const uint32_t* b) {
    asm volatile(
        "mma.sync.aligned.m16n8k8.row.col.f32.tf32.tf32.f32 "
        "{%0,%1,%2,%3}, {%4,%5,%6,%7}, {%8,%9}, {%0,%1,%2,%3};\n"
        : "+f"(d[0]), "+f"(d[1]), "+f"(d[2]), "+f"(d[3])
        : "r"(a[0]), "r"(a[1]), "r"(a[2]), "r"(a[3]),
          "r"(b[0]), "r"(b[1]));
}

// ===========================================================================
// TF32 tensor-core GEMM (NT): C[M,N] = A[M,K] * B[N,K]^T (+ bias[N]).
// (unchanged from R10 passing kernel)
// ===========================================================================
#define BM 128
#define BN 128
#define BK 32
#define KST 36

__global__ __launch_bounds__(256, 2)
void gemm_tf32_nt(const float* __restrict__ A, const float* __restrict__ B,
                  float* __restrict__ C, const float* __restrict__ bias,
                  int M, int N, int K)
{
    __shared__ uint32_t As[BM * KST];
    __shared__ uint32_t Bs[BN * KST];

    const int tid  = threadIdx.x;
    const int lane = tid & 31;
    const int warp = tid >> 5;
    const int gid  = lane >> 2;
    const int tig  = lane & 3;
    const int wm   = warp & 3;
    const int wn   = warp >> 2;
    const int m0   = blockIdx.y * BM;
    const int n0   = blockIdx.x * BN;

    float acc[2][8][4];
#pragma unroll
    for (int mt = 0; mt < 2; mt++)
#pragma unroll
        for (int nt = 0; nt < 8; nt++)
#pragma unroll
            for (int r = 0; r < 4; r++) acc[mt][nt][r] = 0.0f;

    for (int k0 = 0; k0 < K; k0 += BK) {
        __syncthreads();
#pragma unroll
        for (int it = 0; it < 4; it++) {
            const int idx = tid + it * 256;
            const int m  = idx >> 3;
            const int kq = (idx & 7) << 2;
            float4 va = *(const float4*)(A + (size_t)(m0 + m) * K + k0 + kq);
            uint4 ua = make_uint4(f2tf(va.x), f2tf(va.y), f2tf(va.z), f2tf(va.w));
            *(uint4*)&As[m * KST + kq] = ua;
            float4 vb = *(const float4*)(B + (size_t)(n0 + m) * K + k0 + kq);
            uint4 ub = make_uint4(f2tf(vb.x), f2tf(vb.y), f2tf(vb.z), f2tf(vb.w));
            *(uint4*)&Bs[m * KST + kq] = ub;
        }
        __syncthreads();

#pragma unroll
        for (int kb = 0; kb < BK; kb += 8) {
            uint32_t a[2][4], b[8][2];
#pragma unroll
            for (int mt = 0; mt < 2; mt++) {
                const int r = wm * 32 + mt * 16 + gid;
                a[mt][0] = As[r * KST + kb + tig];
                a[mt][1] = As[(r + 8) * KST + kb + tig];
                a[mt][2] = As[r * KST + kb + tig + 4];
                a[mt][3] = As[(r + 8) * KST + kb + tig + 4];
            }
#pragma unroll
            for (int nt = 0; nt < 8; nt++) {
                const int c = wn * 64 + nt * 8 + gid;
                b[nt][0] = Bs[c * KST + kb + tig];
                b[nt][1] = Bs[c * KST + kb + tig + 4];
            }
#pragma unroll
            for (int mt = 0; mt < 2; mt++)
#pragma unroll
                for (int nt = 0; nt < 8; nt++)
                    mma_tf32(acc[mt][nt], a[mt], b[nt]);
        }
    }

#pragma unroll
    for (int mt = 0; mt < 2; mt++) {
        const int row = m0 + wm * 32 + mt * 16 + gid;
#pragma unroll
        for (int nt = 0; nt < 8; nt++) {
            const int col = n0 + wn * 64 + nt * 8 + tig * 2;
            const float b0 = bias ? bias[col] : 0.0f;
            const float b1 = bias ? bias[col + 1] : 0.0f;
            float2 v0 = make_float2(acc[mt][nt][0] + b0, acc[mt][nt][1] + b1);
            float2 v1 = make_float2(acc[mt][nt][2] + b0, acc[mt][nt][3] + b1);
            *(float2*)(C + (size_t)row * N + col)       = v0;
            *(float2*)(C + (size_t)(row + 8) * N + col) = v1;
        }
    }
}

// ===========================================================================
// TF32 tensor-core flash attention.
// Block = 1 head x 128 queries, 256 threads (8 warps).  Warp w owns query
// rows [w*16, w*16+16).  KV tiles of 64 keys.
//   S = Q K^T : mma m16n8k8, warp tile 16x64, K=Dh=128
//   softmax   : fragment registers; each row lives in 4 lanes (fixed gid),
//               reductions = 2x shfl.xor.  NO block sync needed.
//   O += P V  : P in per-warp smem rows (only __syncwarp), V natural [k][d].
// Smem strides (u32 units): Q/K 132 (=4 mod 32), V 136 (=8 mod 32), P 68
// (=4 mod 32) -> all fragment LDS and all tile STS conflict-free (verified
// bank maps: QK frags gid*4+tig+kb; V frags tig*8+gid; loaders sweep 0..31).
// ===========================================================================
#define FA_QST 132
#define FA_KST 132
#define FA_VST 136
#define FA_PST 68
#define FA_SMEM_U32 (128 * FA_QST + 64 * FA_KST + 64 * FA_VST + 128 * FA_PST)
#define FA_SMEM_BYTES (FA_SMEM_U32 * 4)

__global__ __launch_bounds__(256, 1)
void flash_attn_tf32(const float* __restrict__ Qg, const float* __restrict__ Kg,
                     const float* __restrict__ Vg, const float* __restrict__ mask,
                     float* __restrict__ Og)
{
    extern __shared__ uint32_t sm[];
    uint32_t* Qs = sm;                       // [128][132]
    uint32_t* Ks = Qs + 128 * FA_QST;        // [64][132]
    uint32_t* Vs = Ks + 64 * FA_KST;         // [64][136]
    uint32_t* Ps = Vs + 64 * FA_VST;         // [128][68]

    const int tid  = threadIdx.x;
    const int lane = tid & 31;
    const int warp = tid >> 5;
    const int gid  = lane >> 2;
    const int tig  = lane & 3;
    const int h    = blockIdx.y;
    const int q0   = blockIdx.x * 128;
    const int hoff = h * DHEAD;
    const float scale = 0.08838834764831845f;  // 1/sqrt(128)

    // Load Q tile (128 x 128), convert to tf32
#pragma unroll
    for (int t = 0; t < 16; t++) {
        const int idx = tid + t * 256;
        const int row = idx >> 5;
        const int c4  = (idx & 31) << 2;
        float4 v = *(const float4*)&Qg[(size_t)(q0 + row) * HID + hoff + c4];
        *(uint4*)&Qs[row * FA_QST + c4] =
            make_uint4(f2tf(v.x), f2tf(v.y), f2tf(v.z), f2tf(v.w));
    }

    const int r0 = warp * 16 + gid;   // fragment row 0 (within 128-row tile)
    const int r1 = r0 + 8;            // fragment row 1

    float m0 = -INFINITY, m1 = -INFINITY, l0 = 0.0f, l1 = 0.0f;
    float o[16][4];
#pragma unroll
    for (int nt = 0; nt < 16; nt++)
#pragma unroll
        for (int r = 0; r < 4; r++) o[nt][r] = 0.0f;

    for (int j0 = 0; j0 < SEQ; j0 += 64) {
        __syncthreads();   // prev iter's K/V reads done (also covers Q on iter 0)
        // Load K,V tiles (64 x 128 each)
#pragma unroll
        for (int t = 0; t < 8; t++) {
            const int idx = tid + t * 256;
            const int row = idx >> 5;
            const int c4  = (idx & 31) << 2;
            float4 vk = *(const float4*)&Kg[(size_t)(j0 + row) * HID + hoff + c4];
            *(uint4*)&Ks[row * FA_KST + c4] =
                make_uint4(f2tf(vk.x), f2tf(vk.y), f2tf(vk.z), f2tf(vk.w));
            float4 vv = *(const float4*)&Vg[(size_t)(j0 + row) * HID + hoff + c4];
            *(uint4*)&Vs[row * FA_VST + c4] =
                make_uint4(f2tf(vv.x), f2tf(vv.y), f2tf(vv.z), f2tf(vv.w));
        }
        __syncthreads();

        // ---- S = Q K^T (warp tile 16x64) ----
        float s[8][4];
#pragma unroll
        for (int nt = 0; nt < 8; nt++)
#pragma unroll
            for (int r = 0; r < 4; r++) s[nt][r] = 0.0f;

#pragma unroll
        for (int kb = 0; kb < 128; kb += 8) {
            uint32_t a[4];
            a[0] = Qs[r0 * FA_QST + kb + tig];
            a[1] = Qs[r1 * FA_QST + kb + tig];
            a[2] = Qs[r0 * FA_QST + kb + tig + 4];
            a[3] = Qs[r1 * FA_QST + kb + tig + 4];
#pragma unroll
            for (int nt = 0; nt < 8; nt++) {
                uint32_t b[2];
                const int c = nt * 8 + gid;
                b[0] = Ks[c * FA_KST + kb + tig];
                b[1] = Ks[c * FA_KST + kb + tig + 4];
                mma_tf32(s[nt], a, b);
            }
        }

        // ---- scale + mask ----
        const float* mrow0 = mask + (size_t)(q0 + r0) * SEQ + j0;
        const float* mrow1 = mask + (size_t)(q0 + r1) * SEQ + j0;
#pragma unroll
        for (int nt = 0; nt < 8; nt++) {
            const int c = nt * 8 + tig * 2;
            float2 mk0 = *(const float2*)(mrow0 + c);
            float2 mk1 = *(const float2*)(mrow1 + c);
            s[nt][0] = s[nt][0] * scale + mk0.x;
            s[nt][1] = s[nt][1] * scale + mk0.y;
            s[nt][2] = s[nt][2] * scale + mk1.x;
            s[nt][3] = s[nt][3] * scale + mk1.y;
        }

        // ---- online softmax (rows r0, r1; reduce across 4 tig lanes) ----
        float mx0 = -INFINITY, mx1 = -INFINITY;
#pragma unroll
        for (int nt = 0; nt < 8; nt++) {
            mx0 = fmaxf(mx0, fmaxf(s[nt][0], s[nt][1]));
            mx1 = fmaxf(mx1, fmaxf(s[nt][2], s[nt][3]));
        }
#pragma unroll
        for (int w = 1; w <= 2; w <<= 1) {
            mx0 = fmaxf(mx0, __shfl_xor_sync(0xffffffffu, mx0, w));
            mx1 = fmaxf(mx1, __shfl_xor_sync(0xffffffffu, mx1, w));
        }
        const float mn0 = fmaxf(m0, mx0);
        const float mn1 = fmaxf(m1, mx1);
        const float al0 = __expf(m0 - mn0);
        const float al1 = __expf(m1 - mn1);
        m0 = mn0; m1 = mn1;

        float sum0 = 0.0f, sum1 = 0.0f;
#pragma unroll
        for (int nt = 0; nt < 8; nt++) {
            s[nt][0] = __expf(s[nt][0] - mn0);
            s[nt][1] = __expf(s[nt][1] - mn0);
            s[nt][2] = __expf(s[nt][2] - mn1);
            s[nt][3] = __expf(s[nt][3] - mn1);
            sum0 += s[nt][0] + s[nt][1];
            sum1 += s[nt][2] + s[nt][3];
        }
#pragma unroll
        for (int w = 1; w <= 2; w <<= 1) {
            sum0 += __shfl_xor_sync(0xffffffffu, sum0, w);
            sum1 += __shfl_xor_sync(0xffffffffu, sum1, w);
        }
        l0 = l0 * al0 + sum0;
        l1 = l1 * al1 + sum1;

        // rescale O accumulators
#pragma unroll
        for (int nt = 0; nt < 16; nt++) {
            o[nt][0] *= al0; o[nt][1] *= al0;
            o[nt][2] *= al1; o[nt][3] *= al1;
        }

        // ---- P -> smem (per-warp rows, tf32) ----
#pragma unroll
        for (int nt = 0; nt < 8; nt++) {
            const int c = nt * 8 + tig * 2;
            *(uint2*)&Ps[r0 * FA_PST + c] = make_uint2(f2tf(s[nt][0]), f2tf(s[nt][1]));
            *(uint2*)&Ps[r1 * FA_PST + c] = make_uint2(f2tf(s[nt][2]), f2tf(s[nt][3]));
        }
        __syncwarp();

        // ---- O += P V  (warp tile 16x128, K=64) ----
#pragma unroll
        for (int kb = 0; kb < 64; kb += 8) {
            uint32_t a[4];
            a[0] = Ps[r0 * FA_PST + kb + tig];
            a[1] = Ps[r1 * FA_PST + kb + tig];
            a[2] = Ps[r0 * FA_PST + kb + tig + 4];
            a[3] = Ps[r1 * FA_PST + kb + tig + 4];
#pragma unroll
            for (int nt = 0; nt < 16; nt++) {
                uint32_t b[2];
                const int d = nt * 8 + gid;
                b[0] = Vs[(kb + tig) * FA_VST + d];
                b[1] = Vs[(kb + tig + 4) * FA_VST + d];
                mma_tf32(o[nt], a, b);
            }
        }
        __syncwarp();  // WAR: next iter rewrites Ps rows other lanes just read
    }

    // ---- normalize + write (merge heads) ----
    const float inv0 = 1.0f / l0;
    const float inv1 = 1.0f / l1;
    float* out0 = Og + (size_t)(q0 + r0) * HID + hoff;
    float* out1 = Og + (size_t)(q0 + r1) * HID + hoff;
#pragma unroll
    for (int nt = 0; nt < 16; nt++) {
        const int d = nt * 8 + tig * 2;
        *(float2*)(out0 + d) = make_float2(o[nt][0] * inv0, o[nt][1] * inv0);
        *(float2*)(out1 + d) = make_float2(o[nt][2] * inv1, o[nt][3] * inv1);
    }
}

// ---------------------------------------------------------------------------
// Launch: 3x (x @ V^T) -> 3x (t @ U^T) -> tf32 flash attention -> (o @ W^T + b)
// ---------------------------------------------------------------------------
extern "C" void kernel_launch(void* const* d_in, const int* in_sizes, int n_in,
                              void* d_out, int out_size)
{
    (void)in_sizes; (void)n_in; (void)out_size;
    const float* x    = (const float*)d_in[0];
    const float* mask = (const float*)d_in[1];
    const float* Vw[3] = { (const float*)d_in[2], (const float*)d_in[4], (const float*)d_in[6] };
    const float* Uw[3] = { (const float*)d_in[3], (const float*)d_in[5], (const float*)d_in[7] };
    const float* oW = (const float*)d_in[8];
    const float* ob = (const float*)d_in[9];
    float* out = (float*)d_out;

    void *pT, *pQKV, *pAO;
    cudaGetSymbolAddress(&pT, g_T);
    cudaGetSymbolAddress(&pQKV, g_QKV);
    cudaGetSymbolAddress(&pAO, g_AO);
    float* T   = (float*)pT;
    float* QKV = (float*)pQKV;
    float* AO  = (float*)pAO;

    cudaFuncSetAttribute(flash_attn_tf32, cudaFuncAttributeMaxDynamicSharedMemorySize,
                         FA_SMEM_BYTES);

    // Stage 1: T_i = X @ V_i^T
    {
        dim3 grid(RNK / BN, SEQ / BM);
        for (int i = 0; i < 3; i++)
            gemm_tf32_nt<<<grid, 256>>>(x, Vw[i], T + (size_t)i * SEQ * RNK, nullptr,
                                        SEQ, RNK, HID);
    }
    // Stage 2: QKV_i = T_i @ U_i^T
    {
        dim3 grid(HID / BN, SEQ / BM);
        for (int i = 0; i < 3; i++)
            gemm_tf32_nt<<<grid, 256>>>(T + (size_t)i * SEQ * RNK, Uw[i],
                                        QKV + (size_t)i * SEQ * HID, nullptr,
                                        SEQ, HID, RNK);
    }
    // Stage 3: attention
    {
        dim3 grid(SEQ / 128, NHEAD);
        flash_attn_tf32<<<grid, 256, FA_SMEM_BYTES>>>(
            QKV, QKV + (size_t)SEQ * HID, QKV + (size_t)2 * SEQ * HID, mask, AO);
    }
    // Stage 4: out = AO @ oW^T + ob
    {
        dim3 grid(HID / BN, SEQ / BM);
        gemm_tf32_nt<<<grid, 256>>>(AO, oW, out, ob, SEQ, HID, HID);
    }
}

// round 12
// speedup vs baseline: 4.9393x; 1.1420x over previous
#include <cuda_runtime.h>
#include <math.h>
#include <stdint.h>

// Problem constants
#define SEQ   4096
#define HID   2048
#define RNK   1024
#define NHEAD 16
#define DHEAD 128

// Scratch (device globals: allocation-free per harness rules)
__device__ float g_T[3 * SEQ * RNK];
__device__ float g_QKV[3 * SEQ * HID];
__device__ float g_AO[SEQ * HID];

__device__ __forceinline__ uint32_t f2tf(float x) {
    uint32_t r;
    asm("cvt.rna.tf32.f32 %0, %1;" : "=r"(r) : "f"(x));
    return r;
}

__device__ __forceinline__ void mma_tf32(float* d, const uint32_t* a, const uint32_t* b) {
    asm volatile(
        "mma.sync.aligned.m16n8k8.row.col.f32.tf32.tf32.f32 "
        "{%0,%1,%2,%3}, {%4,%5,%6,%7}, {%8,%9}, {%0,%1,%2,%3};\n"
        : "+f"(d[0]), "+f"(d[1]), "+f"(d[2]), "+f"(d[3])
        : "r"(a[0]), "r"(a[1]), "r"(a[2]), "r"(a[3]),
          "r"(b[0]), "r"(b[1]));
}

__device__ __forceinline__ uint32_t smem_u32(const void* p) {
    return (uint32_t)__cvta_generic_to_shared(p);
}
__device__ __forceinline__ void cp_async16(uint32_t s, const void* g) {
    asm volatile("cp.async.cg.shared.global [%0], [%1], 16;\n"
                 :: "r"(s), "l"(g) : "memory");
}
__device__ __forceinline__ void cp_commit() {
    asm volatile("cp.async.commit_group;\n" ::: "memory");
}
template<int N> __device__ __forceinline__ void cp_wait() {
    asm volatile("cp.async.wait_group %0;\n" :: "n"(N) : "memory");
}

// ===========================================================================
// TF32 GEMM (NT), cp.async double-buffered.  C = A[M,K] * B[N,K]^T (+bias).
// Tile 128x128x32, 256 threads, warp tile 32x64, m16n8k8 fragments.
// Smem (dynamic): As[2][128*36] ++ Bs[2][128*36]  = 73728 B, 2 CTAs/SM.
// Operands enter mma as raw fp32 (HW tf32 truncation).
// ===========================================================================
#define BM 128
#define BN 128
#define BK 32
#define KST 36
#define GEMM_SMEM_BYTES (4 * BM * KST * 4)   // 2 bufs x (A+B) tiles

__global__ __launch_bounds__(256, 2)
void gemm_tf32_nt(const float* __restrict__ A, const float* __restrict__ B,
                  float* __restrict__ C, const float* __restrict__ bias,
                  int M, int N, int K)
{
    extern __shared__ uint32_t dyn[];
    uint32_t* AsBase = dyn;                    // [2][BM*KST]
    uint32_t* BsBase = dyn + 2 * BM * KST;     // [2][BN*KST]

    const int tid  = threadIdx.x;
    const int lane = tid & 31;
    const int warp = tid >> 5;
    const int gid  = lane >> 2;
    const int tig  = lane & 3;
    const int wm   = warp & 3;
    const int wn   = warp >> 2;
    const int m0   = blockIdx.y * BM;
    const int n0   = blockIdx.x * BN;
    const int NT   = K / BK;

    // loader coords
    const int lm = tid >> 3;             // 0..31 (row block of 128 via 4 its)
    const int lk = (tid & 7) << 2;       // 0,4,...,28

    float acc[2][8][4];
#pragma unroll
    for (int mt = 0; mt < 2; mt++)
#pragma unroll
        for (int nt = 0; nt < 8; nt++)
#pragma unroll
            for (int r = 0; r < 4; r++) acc[mt][nt][r] = 0.0f;

    // prologue: tile 0 -> buf 0
    {
#pragma unroll
        for (int it = 0; it < 4; it++) {
            const int m = lm + it * 32;
            cp_async16(smem_u32(&AsBase[m * KST + lk]), A + (size_t)(m0 + m) * K + lk);
            cp_async16(smem_u32(&BsBase[m * KST + lk]), B + (size_t)(n0 + m) * K + lk);
        }
        cp_commit();
    }

    for (int j = 0; j < NT; j++) {
        const int buf = j & 1;
        __syncthreads();   // all threads done computing tile j-1 (buf^1 reusable)
        if (j + 1 < NT) {
            const int k0 = (j + 1) * BK;
            uint32_t* An = AsBase + (buf ^ 1) * BM * KST;
            uint32_t* Bn = BsBase + (buf ^ 1) * BN * KST;
#pragma unroll
            for (int it = 0; it < 4; it++) {
                const int m = lm + it * 32;
                cp_async16(smem_u32(&An[m * KST + lk]), A + (size_t)(m0 + m) * K + k0 + lk);
                cp_async16(smem_u32(&Bn[m * KST + lk]), B + (size_t)(n0 + m) * K + k0 + lk);
            }
            cp_commit();
            cp_wait<1>();
        } else {
            cp_wait<0>();
        }
        __syncthreads();   // tile j visible to all

        const uint32_t* As = AsBase + buf * BM * KST;
        const uint32_t* Bs = BsBase + buf * BN * KST;
#pragma unroll
        for (int kb = 0; kb < BK; kb += 8) {
            uint32_t a[2][4], b[8][2];
#pragma unroll
            for (int mt = 0; mt < 2; mt++) {
                const int r = wm * 32 + mt * 16 + gid;
                a[mt][0] = As[r * KST + kb + tig];
                a[mt][1] = As[(r + 8) * KST + kb + tig];
                a[mt][2] = As[r * KST + kb + tig + 4];
                a[mt][3] = As[(r + 8) * KST + kb + tig + 4];
            }
#pragma unroll
            for (int nt = 0; nt < 8; nt++) {
                const int c = wn * 64 + nt * 8 + gid;
                b[nt][0] = Bs[c * KST + kb + tig];
                b[nt][1] = Bs[c * KST + kb + tig + 4];
            }
#pragma unroll
            for (int mt = 0; mt < 2; mt++)
#pragma unroll
                for (int nt = 0; nt < 8; nt++)
                    mma_tf32(acc[mt][nt], a[mt], b[nt]);
        }
    }

#pragma unroll
    for (int mt = 0; mt < 2; mt++) {
        const int row = m0 + wm * 32 + mt * 16 + gid;
#pragma unroll
        for (int nt = 0; nt < 8; nt++) {
            const int col = n0 + wn * 64 + nt * 8 + tig * 2;
            const float b0 = bias ? bias[col] : 0.0f;
            const float b1 = bias ? bias[col + 1] : 0.0f;
            float2 v0 = make_float2(acc[mt][nt][0] + b0, acc[mt][nt][1] + b1);
            float2 v1 = make_float2(acc[mt][nt][2] + b0, acc[mt][nt][3] + b1);
            *(float2*)(C + (size_t)row * N + col)       = v0;
            *(float2*)(C + (size_t)(row + 8) * N + col) = v1;
        }
    }
}

// ===========================================================================
// TF32 flash attention, cp.async double-buffered K/V, shuffle-P (no P smem).
// Block = 1 head x 128 queries, 8 warps; warp owns 16 query rows.
// Smem: Q[128*132] + K[2][64*132] + V[2][64*136] = 204800 B (1 CTA/SM).
// ===========================================================================
#define FA_QST 132
#define FA_KST 132
#define FA_VST 136
#define FA_SMEM_U32 (128 * FA_QST + 2 * 64 * FA_KST + 2 * 64 * FA_VST)
#define FA_SMEM_BYTES (FA_SMEM_U32 * 4)
#define FA_NT (SEQ / 64)

__global__ __launch_bounds__(256, 1)
void flash_attn_tf32(const float* __restrict__ Qg, const float* __restrict__ Kg,
                     const float* __restrict__ Vg, const float* __restrict__ mask,
                     float* __restrict__ Og)
{
    extern __shared__ uint32_t sm[];
    uint32_t* Qs  = sm;                         // [128][132]
    uint32_t* Ks0 = Qs + 128 * FA_QST;          // [2][64][132]
    uint32_t* Vs0 = Ks0 + 2 * 64 * FA_KST;      // [2][64][136]

    const int tid  = threadIdx.x;
    const int lane = tid & 31;
    const int warp = tid >> 5;
    const int gid  = lane >> 2;
    const int tig  = lane & 3;
    const int h    = blockIdx.y;
    const int q0   = blockIdx.x * 128;
    const int hoff = h * DHEAD;
    const float scale = 0.08838834764831845f;  // 1/sqrt(128)

    // KV loader coords (8 chunks of 16B per thread per tile)
    const int krow = tid >> 5;          // base row 0..7
    const int kc4  = (tid & 31) << 2;   // 0..124 step 4

    // prologue: issue K/V tile 0 into buf 0, then stage Q (overlaps loads)
    {
#pragma unroll
        for (int t = 0; t < 8; t++) {
            const int row = krow + t * 8;
            cp_async16(smem_u32(&Ks0[row * FA_KST + kc4]),
                       Kg + (size_t)row * HID + hoff + kc4);
            cp_async16(smem_u32(&Vs0[row * FA_VST + kc4]),
                       Vg + (size_t)row * HID + hoff + kc4);
        }
        cp_commit();
    }
#pragma unroll
    for (int t = 0; t < 16; t++) {
        const int idx = tid + t * 256;
        const int row = idx >> 5;
        const int c4  = (idx & 31) << 2;
        float4 v = *(const float4*)&Qg[(size_t)(q0 + row) * HID + hoff + c4];
        *(uint4*)&Qs[row * FA_QST + c4] =
            make_uint4(f2tf(v.x), f2tf(v.y), f2tf(v.z), f2tf(v.w));
    }

    const int r0 = warp * 16 + gid;
    const int r1 = r0 + 8;
    const float* mbase0 = mask + (size_t)(q0 + r0) * SEQ;
    const float* mbase1 = mask + (size_t)(q0 + r1) * SEQ;
    const int shsrc  = (lane & 28) | (tig >> 1);
    const int shsrc2 = shsrc + 2;
    const bool odd = tig & 1;

    float m0 = -INFINITY, m1 = -INFINITY, l0 = 0.0f, l1 = 0.0f;
    float o[16][4];
#pragma unroll
    for (int nt = 0; nt < 16; nt++)
#pragma unroll
        for (int r = 0; r < 4; r++) o[nt][r] = 0.0f;

    for (int j = 0; j < FA_NT; j++) {
        const int buf = j & 1;
        const int j0  = j * 64;
        __syncthreads();   // all threads done with tile j-1 buffers (+ Q on j=0)
        if (j + 1 < FA_NT) {
            const int jn = (j + 1) * 64;
            uint32_t* Kn = Ks0 + (buf ^ 1) * 64 * FA_KST;
            uint32_t* Vn = Vs0 + (buf ^ 1) * 64 * FA_VST;
#pragma unroll
            for (int t = 0; t < 8; t++) {
                const int row = krow + t * 8;
                cp_async16(smem_u32(&Kn[row * FA_KST + kc4]),
                           Kg + (size_t)(jn + row) * HID + hoff + kc4);
                cp_async16(smem_u32(&Vn[row * FA_VST + kc4]),
                           Vg + (size_t)(jn + row) * HID + hoff + kc4);
            }
            cp_commit();
        }
        // mask prefetch (LDG latency overlaps the cp.async wait + barrier)
        float2 mk0[8], mk1[8];
#pragma unroll
        for (int nt = 0; nt < 8; nt++) {
            const int c = j0 + nt * 8 + tig * 2;
            mk0[nt] = *(const float2*)(mbase0 + c);
            mk1[nt] = *(const float2*)(mbase1 + c);
        }
        if (j + 1 < FA_NT) cp_wait<1>(); else cp_wait<0>();
        __syncthreads();   // tile j visible

        const uint32_t* Ksb = Ks0 + buf * 64 * FA_KST;
        const uint32_t* Vsb = Vs0 + buf * 64 * FA_VST;

        // ---- S = Q K^T ----
        float s[8][4];
#pragma unroll
        for (int nt = 0; nt < 8; nt++)
#pragma unroll
            for (int r = 0; r < 4; r++) s[nt][r] = 0.0f;
#pragma unroll
        for (int kb = 0; kb < 128; kb += 8) {
            uint32_t a[4];
            a[0] = Qs[r0 * FA_QST + kb + tig];
            a[1] = Qs[r1 * FA_QST + kb + tig];
            a[2] = Qs[r0 * FA_QST + kb + tig + 4];
            a[3] = Qs[r1 * FA_QST + kb + tig + 4];
#pragma unroll
            for (int nt = 0; nt < 8; nt++) {
                uint32_t b[2];
                const int c = nt * 8 + gid;
                b[0] = Ksb[c * FA_KST + kb + tig];
                b[1] = Ksb[c * FA_KST + kb + tig + 4];
                mma_tf32(s[nt], a, b);
            }
        }

        // ---- scale + mask ----
#pragma unroll
        for (int nt = 0; nt < 8; nt++) {
            s[nt][0] = s[nt][0] * scale + mk0[nt].x;
            s[nt][1] = s[nt][1] * scale + mk0[nt].y;
            s[nt][2] = s[nt][2] * scale + mk1[nt].x;
            s[nt][3] = s[nt][3] * scale + mk1[nt].y;
        }

        // ---- online softmax (reduce across 4 tig lanes) ----
        float mx0 = -INFINITY, mx1 = -INFINITY;
#pragma unroll
        for (int nt = 0; nt < 8; nt++) {
            mx0 = fmaxf(mx0, fmaxf(s[nt][0], s[nt][1]));
            mx1 = fmaxf(mx1, fmaxf(s[nt][2], s[nt][3]));
        }
#pragma unroll
        for (int w = 1; w <= 2; w <<= 1) {
            mx0 = fmaxf(mx0, __shfl_xor_sync(0xffffffffu, mx0, w));
            mx1 = fmaxf(mx1, __shfl_xor_sync(0xffffffffu, mx1, w));
        }
        const float mn0 = fmaxf(m0, mx0);
        const float mn1 = fmaxf(m1, mx1);
        const float al0 = __expf(m0 - mn0);
        const float al1 = __expf(m1 - mn1);
        m0 = mn0; m1 = mn1;

        float sum0 = 0.0f, sum1 = 0.0f;
#pragma unroll
        for (int nt = 0; nt < 8; nt++) {
            s[nt][0] = __expf(s[nt][0] - mn0);
            s[nt][1] = __expf(s[nt][1] - mn0);
            s[nt][2] = __expf(s[nt][2] - mn1);
            s[nt][3] = __expf(s[nt][3] - mn1);
            sum0 += s[nt][0] + s[nt][1];
            sum1 += s[nt][2] + s[nt][3];
        }
#pragma unroll
        for (int w = 1; w <= 2; w <<= 1) {
            sum0 += __shfl_xor_sync(0xffffffffu, sum0, w);
            sum1 += __shfl_xor_sync(0xffffffffu, sum1, w);
        }
        l0 = l0 * al0 + sum0;
        l1 = l1 * al1 + sum1;
#pragma unroll
        for (int nt = 0; nt < 16; nt++) {
            o[nt][0] *= al0; o[nt][1] *= al0;
            o[nt][2] *= al1; o[nt][3] *= al1;
        }

        // ---- O += P V : S-fragment -> A-fragment via intra-quad shuffles ----
#pragma unroll
        for (int g = 0; g < 8; g++) {
            const float t0 = __shfl_sync(0xffffffffu, s[g][0], shsrc);
            const float t1 = __shfl_sync(0xffffffffu, s[g][1], shsrc);
            const float t2 = __shfl_sync(0xffffffffu, s[g][2], shsrc);
            const float t3 = __shfl_sync(0xffffffffu, s[g][3], shsrc);
            const float u0 = __shfl_sync(0xffffffffu, s[g][0], shsrc2);
            const float u1 = __shfl_sync(0xffffffffu, s[g][1], shsrc2);
            const float u2 = __shfl_sync(0xffffffffu, s[g][2], shsrc2);
            const float u3 = __shfl_sync(0xffffffffu, s[g][3], shsrc2);
            uint32_t a[4];
            a[0] = f2tf(odd ? t1 : t0);
            a[1] = f2tf(odd ? t3 : t2);
            a[2] = f2tf(odd ? u1 : u0);
            a[3] = f2tf(odd ? u3 : u2);
            const int kb = g * 8;
#pragma unroll
            for (int nt = 0; nt < 16; nt++) {
                uint32_t b[2];
                const int d = nt * 8 + gid;
                b[0] = Vsb[(kb + tig) * FA_VST + d];
                b[1] = Vsb[(kb + tig + 4) * FA_VST + d];
                mma_tf32(o[nt], a, b);
            }
        }
    }

    // ---- normalize + write (merge heads) ----
    const float inv0 = 1.0f / l0;
    const float inv1 = 1.0f / l1;
    float* out0 = Og + (size_t)(q0 + r0) * HID + hoff;
    float* out1 = Og + (size_t)(q0 + r1) * HID + hoff;
#pragma unroll
    for (int nt = 0; nt < 16; nt++) {
        const int d = nt * 8 + tig * 2;
        *(float2*)(out0 + d) = make_float2(o[nt][0] * inv0, o[nt][1] * inv0);
        *(float2*)(out1 + d) = make_float2(o[nt][2] * inv1, o[nt][3] * inv1);
    }
}

// ---------------------------------------------------------------------------
// Launch
// ---------------------------------------------------------------------------
extern "C" void kernel_launch(void* const* d_in, const int* in_sizes, int n_in,
                              void* d_out, int out_size)
{
    (void)in_sizes; (void)n_in; (void)out_size;
    const float* x    = (const float*)d_in[0];
    const float* mask = (const float*)d_in[1];
    const float* Vw[3] = { (const float*)d_in[2], (const float*)d_in[4], (const float*)d_in[6] };
    const float* Uw[3] = { (const float*)d_in[3], (const float*)d_in[5], (const float*)d_in[7] };
    const float* oW = (const float*)d_in[8];
    const float* ob = (const float*)d_in[9];
    float* out = (float*)d_out;

    void *pT, *pQKV, *pAO;
    cudaGetSymbolAddress(&pT, g_T);
    cudaGetSymbolAddress(&pQKV, g_QKV);
    cudaGetSymbolAddress(&pAO, g_AO);
    float* T   = (float*)pT;
    float* QKV = (float*)pQKV;
    float* AO  = (float*)pAO;

    cudaFuncSetAttribute(gemm_tf32_nt, cudaFuncAttributeMaxDynamicSharedMemorySize,
                         GEMM_SMEM_BYTES);
    cudaFuncSetAttribute(flash_attn_tf32, cudaFuncAttributeMaxDynamicSharedMemorySize,
                         FA_SMEM_BYTES);

    // Stage 1: T_i = X @ V_i^T
    {
        dim3 grid(RNK / BN, SEQ / BM);
        for (int i = 0; i < 3; i++)
            gemm_tf32_nt<<<grid, 256, GEMM_SMEM_BYTES>>>(
                x, Vw[i], T + (size_t)i * SEQ * RNK, nullptr, SEQ, RNK, HID);
    }
    // Stage 2: QKV_i = T_i @ U_i^T
    {
        dim3 grid(HID / BN, SEQ / BM);
        for (int i = 0; i < 3; i++)
            gemm_tf32_nt<<<grid, 256, GEMM_SMEM_BYTES>>>(
                T + (size_t)i * SEQ * RNK, Uw[i], QKV + (size_t)i * SEQ * HID,
                nullptr, SEQ, HID, RNK);
    }
    // Stage 3: attention
    {
        dim3 grid(SEQ / 128, NHEAD);
        flash_attn_tf32<<<grid, 256, FA_SMEM_BYTES>>>(
            QKV, QKV + (size_t)SEQ * HID, QKV + (size_t)2 * SEQ * HID, mask, AO);
    }
    // Stage 4: out = AO @ oW^T + ob
    {
        dim3 grid(HID / BN, SEQ / BM);
        gemm_tf32_nt<<<grid, 256, GEMM_SMEM_BYTES>>>(AO, oW, out, ob, SEQ, HID, HID);
    }
}

// round 13
// speedup vs baseline: 4.9418x; 1.0005x over previous
#include <cuda_runtime.h>
#include <math.h>
#include <stdint.h>

// Problem constants
#define SEQ   4096
#define HID   2048
#define RNK   1024
#define NHEAD 16
#define DHEAD 128

// Scratch (device globals: allocation-free per harness rules)
__device__ float g_T[3 * SEQ * RNK];
__device__ float g_QKV[3 * SEQ * HID];
__device__ float g_AO[SEQ * HID];

__device__ __forceinline__ uint32_t f2tf(float x) {
    uint32_t r;
    asm("cvt.rna.tf32.f32 %0, %1;" : "=r"(r) : "f"(x));
    return r;
}

__device__ __forceinline__ void mma_tf32(float* d, const uint32_t* a, const uint32_t* b) {
    asm volatile(
        "mma.sync.aligned.m16n8k8.row.col.f32.tf32.tf32.f32 "
        "{%0,%1,%2,%3}, {%4,%5,%6,%7}, {%8,%9}, {%0,%1,%2,%3};\n"
        : "+f"(d[0]), "+f"(d[1]), "+f"(d[2]), "+f"(d[3])
        : "r"(a[0]), "r"(a[1]), "r"(a[2]), "r"(a[3]),
          "r"(b[0]), "r"(b[1]));
}

__device__ __forceinline__ uint32_t smem_u32(const void* p) {
    return (uint32_t)__cvta_generic_to_shared(p);
}
__device__ __forceinline__ void cp_async16(uint32_t s, const void* g) {
    asm volatile("cp.async.cg.shared.global [%0], [%1], 16;\n"
                 :: "r"(s), "l"(g) : "memory");
}
__device__ __forceinline__ void cp_commit() {
    asm volatile("cp.async.commit_group;\n" ::: "memory");
}
template<int N> __device__ __forceinline__ void cp_wait() {
    asm volatile("cp.async.wait_group %0;\n" :: "n"(N) : "memory");
}

// ===========================================================================
// TF32 GEMM (NT), cp.async double-buffered.  C = A[M,K] * B[N,K]^T (+bias).
// Tile 128x128x32, 256 threads, warp tile 32x64, m16n8k8 fragments.
// Smem (dynamic): As[2][128*36] ++ Bs[2][128*36]  = 73728 B, 2 CTAs/SM.
// Operands enter mma as raw fp32 (HW tf32 truncation).
// ===========================================================================
#define BM 128
#define BN 128
#define BK 32
#define KST 36
#define GEMM_SMEM_BYTES (4 * BM * KST * 4)   // 2 bufs x (A+B) tiles

__global__ __launch_bounds__(256, 2)
void gemm_tf32_nt(const float* __restrict__ A, const float* __restrict__ B,
                  float* __restrict__ C, const float* __restrict__ bias,
                  int M, int N, int K)
{
    extern __shared__ uint32_t dyn[];
    uint32_t* AsBase = dyn;                    // [2][BM*KST]
    uint32_t* BsBase = dyn + 2 * BM * KST;     // [2][BN*KST]

    const int tid  = threadIdx.x;
    const int lane = tid & 31;
    const int warp = tid >> 5;
    const int gid  = lane >> 2;
    const int tig  = lane & 3;
    const int wm   = warp & 3;
    const int wn   = warp >> 2;
    const int m0   = blockIdx.y * BM;
    const int n0   = blockIdx.x * BN;
    const int NT   = K / BK;

    // loader coords
    const int lm = tid >> 3;             // 0..31 (row block of 128 via 4 its)
    const int lk = (tid & 7) << 2;       // 0,4,...,28

    float acc[2][8][4];
#pragma unroll
    for (int mt = 0; mt < 2; mt++)
#pragma unroll
        for (int nt = 0; nt < 8; nt++)
#pragma unroll
            for (int r = 0; r < 4; r++) acc[mt][nt][r] = 0.0f;

    // prologue: tile 0 -> buf 0
    {
#pragma unroll
        for (int it = 0; it < 4; it++) {
            const int m = lm + it * 32;
            cp_async16(smem_u32(&AsBase[m * KST + lk]), A + (size_t)(m0 + m) * K + lk);
            cp_async16(smem_u32(&BsBase[m * KST + lk]), B + (size_t)(n0 + m) * K + lk);
        }
        cp_commit();
    }

    for (int j = 0; j < NT; j++) {
        const int buf = j & 1;
        __syncthreads();   // all threads done computing tile j-1 (buf^1 reusable)
        if (j + 1 < NT) {
            const int k0 = (j + 1) * BK;
            uint32_t* An = AsBase + (buf ^ 1) * BM * KST;
            uint32_t* Bn = BsBase + (buf ^ 1) * BN * KST;
#pragma unroll
            for (int it = 0; it < 4; it++) {
                const int m = lm + it * 32;
                cp_async16(smem_u32(&An[m * KST + lk]), A + (size_t)(m0 + m) * K + k0 + lk);
                cp_async16(smem_u32(&Bn[m * KST + lk]), B + (size_t)(n0 + m) * K + k0 + lk);
            }
            cp_commit();
            cp_wait<1>();
        } else {
            cp_wait<0>();
        }
        __syncthreads();   // tile j visible to all

        const uint32_t* As = AsBase + buf * BM * KST;
        const uint32_t* Bs = BsBase + buf * BN * KST;
#pragma unroll
        for (int kb = 0; kb < BK; kb += 8) {
            uint32_t a[2][4], b[8][2];
#pragma unroll
            for (int mt = 0; mt < 2; mt++) {
                const int r = wm * 32 + mt * 16 + gid;
                a[mt][0] = As[r * KST + kb + tig];
                a[mt][1] = As[(r + 8) * KST + kb + tig];
                a[mt][2] = As[r * KST + kb + tig + 4];
                a[mt][3] = As[(r + 8) * KST + kb + tig + 4];
            }
#pragma unroll
            for (int nt = 0; nt < 8; nt++) {
                const int c = wn * 64 + nt * 8 + gid;
                b[nt][0] = Bs[c * KST + kb + tig];
                b[nt][1] = Bs[c * KST + kb + tig + 4];
            }
#pragma unroll
            for (int mt = 0; mt < 2; mt++)
#pragma unroll
                for (int nt = 0; nt < 8; nt++)
                    mma_tf32(acc[mt][nt], a[mt], b[nt]);
        }
    }

#pragma unroll
    for (int mt = 0; mt < 2; mt++) {
        const int row = m0 + wm * 32 + mt * 16 + gid;
#pragma unroll
        for (int nt = 0; nt < 8; nt++) {
            const int col = n0 + wn * 64 + nt * 8 + tig * 2;
            const float b0 = bias ? bias[col] : 0.0f;
            const float b1 = bias ? bias[col + 1] : 0.0f;
            float2 v0 = make_float2(acc[mt][nt][0] + b0, acc[mt][nt][1] + b1);
            float2 v1 = make_float2(acc[mt][nt][2] + b0, acc[mt][nt][3] + b1);
            *(float2*)(C + (size_t)row * N + col)       = v0;
            *(float2*)(C + (size_t)(row + 8) * N + col) = v1;
        }
    }
}

// ===========================================================================
// TF32 flash attention, cp.async double-buffered K/V, shuffle-P (no P smem).
// Block = 1 head x 128 queries, 8 warps; warp owns 16 query rows.
// Smem: Q[128*132] + K[2][64*132] + V[2][64*136] = 204800 B (1 CTA/SM).
// ===========================================================================
#define FA_QST 132
#define FA_KST 132
#define FA_VST 136
#define FA_SMEM_U32 (128 * FA_QST + 2 * 64 * FA_KST + 2 * 64 * FA_VST)
#define FA_SMEM_BYTES (FA_SMEM_U32 * 4)
#define FA_NT (SEQ / 64)

__global__ __launch_bounds__(256, 1)
void flash_attn_tf32(const float* __restrict__ Qg, const float* __restrict__ Kg,
                     const float* __restrict__ Vg, const float* __restrict__ mask,
                     float* __restrict__ Og)
{
    extern __shared__ uint32_t sm[];
    uint32_t* Qs  = sm;                         // [128][132]
    uint32_t* Ks0 = Qs + 128 * FA_QST;          // [2][64][132]
    uint32_t* Vs0 = Ks0 + 2 * 64 * FA_KST;      // [2][64][136]

    const int tid  = threadIdx.x;
    const int lane = tid & 31;
    const int warp = tid >> 5;
    const int gid  = lane >> 2;
    const int tig  = lane & 3;
    const int h    = blockIdx.y;
    const int q0   = blockIdx.x * 128;
    const int hoff = h * DHEAD;
    const float scale = 0.08838834764831845f;  // 1/sqrt(128)

    // KV loader coords (8 chunks of 16B per thread per tile)
    const int krow = tid >> 5;          // base row 0..7
    const int kc4  = (tid & 31) << 2;   // 0..124 step 4

    // prologue: issue K/V tile 0 into buf 0, then stage Q (overlaps loads)
    {
#pragma unroll
        for (int t = 0; t < 8; t++) {
            const int row = krow + t * 8;
            cp_async16(smem_u32(&Ks0[row * FA_KST + kc4]),
                       Kg + (size_t)row * HID + hoff + kc4);
            cp_async16(smem_u32(&Vs0[row * FA_VST + kc4]),
                       Vg + (size_t)row * HID + hoff + kc4);
        }
        cp_commit();
    }
#pragma unroll
    for (int t = 0; t < 16; t++) {
        const int idx = tid + t * 256;
        const int row = idx >> 5;
        const int c4  = (idx & 31) << 2;
        float4 v = *(const float4*)&Qg[(size_t)(q0 + row) * HID + hoff + c4];
        *(uint4*)&Qs[row * FA_QST + c4] =
            make_uint4(f2tf(v.x), f2tf(v.y), f2tf(v.z), f2tf(v.w));
    }

    const int r0 = warp * 16 + gid;
    const int r1 = r0 + 8;
    const float* mbase0 = mask + (size_t)(q0 + r0) * SEQ;
    const float* mbase1 = mask + (size_t)(q0 + r1) * SEQ;
    const int shsrc  = (lane & 28) | (tig >> 1);
    const int shsrc2 = shsrc + 2;
    const bool odd = tig & 1;

    float m0 = -INFINITY, m1 = -INFINITY, l0 = 0.0f, l1 = 0.0f;
    float o[16][4];
#pragma unroll
    for (int nt = 0; nt < 16; nt++)
#pragma unroll
        for (int r = 0; r < 4; r++) o[nt][r] = 0.0f;

    for (int j = 0; j < FA_NT; j++) {
        const int buf = j & 1;
        const int j0  = j * 64;
        __syncthreads();   // all threads done with tile j-1 buffers (+ Q on j=0)
        if (j + 1 < FA_NT) {
            const int jn = (j + 1) * 64;
            uint32_t* Kn = Ks0 + (buf ^ 1) * 64 * FA_KST;
            uint32_t* Vn = Vs0 + (buf ^ 1) * 64 * FA_VST;
#pragma unroll
            for (int t = 0; t < 8; t++) {
                const int row = krow + t * 8;
                cp_async16(smem_u32(&Kn[row * FA_KST + kc4]),
                           Kg + (size_t)(jn + row) * HID + hoff + kc4);
                cp_async16(smem_u32(&Vn[row * FA_VST + kc4]),
                           Vg + (size_t)(jn + row) * HID + hoff + kc4);
            }
            cp_commit();
        }
        // mask prefetch (LDG latency overlaps the cp.async wait + barrier)
        float2 mk0[8], mk1[8];
#pragma unroll
        for (int nt = 0; nt < 8; nt++) {
            const int c = j0 + nt * 8 + tig * 2;
            mk0[nt] = *(const float2*)(mbase0 + c);
            mk1[nt] = *(const float2*)(mbase1 + c);
        }
        if (j + 1 < FA_NT) cp_wait<1>(); else cp_wait<0>();
        __syncthreads();   // tile j visible

        const uint32_t* Ksb = Ks0 + buf * 64 * FA_KST;
        const uint32_t* Vsb = Vs0 + buf * 64 * FA_VST;

        // ---- S = Q K^T ----
        float s[8][4];
#pragma unroll
        for (int nt = 0; nt < 8; nt++)
#pragma unroll
            for (int r = 0; r < 4; r++) s[nt][r] = 0.0f;
#pragma unroll
        for (int kb = 0; kb < 128; kb += 8) {
            uint32_t a[4];
            a[0] = Qs[r0 * FA_QST + kb + tig];
            a[1] = Qs[r1 * FA_QST + kb + tig];
            a[2] = Qs[r0 * FA_QST + kb + tig + 4];
            a[3] = Qs[r1 * FA_QST + kb + tig + 4];
#pragma unroll
            for (int nt = 0; nt < 8; nt++) {
                uint32_t b[2];
                const int c = nt * 8 + gid;
                b[0] = Ksb[c * FA_KST + kb + tig];
                b[1] = Ksb[c * FA_KST + kb + tig + 4];
                mma_tf32(s[nt], a, b);
            }
        }

        // ---- scale + mask ----
#pragma unroll
        for (int nt = 0; nt < 8; nt++) {
            s[nt][0] = s[nt][0] * scale + mk0[nt].x;
            s[nt][1] = s[nt][1] * scale + mk0[nt].y;
            s[nt][2] = s[nt][2] * scale + mk1[nt].x;
            s[nt][3] = s[nt][3] * scale + mk1[nt].y;
        }

        // ---- online softmax (reduce across 4 tig lanes) ----
        float mx0 = -INFINITY, mx1 = -INFINITY;
#pragma unroll
        for (int nt = 0; nt < 8; nt++) {
            mx0 = fmaxf(mx0, fmaxf(s[nt][0], s[nt][1]));
            mx1 = fmaxf(mx1, fmaxf(s[nt][2], s[nt][3]));
        }
#pragma unroll
        for (int w = 1; w <= 2; w <<= 1) {
            mx0 = fmaxf(mx0, __shfl_xor_sync(0xffffffffu, mx0, w));
            mx1 = fmaxf(mx1, __shfl_xor_sync(0xffffffffu, mx1, w));
        }
        const float mn0 = fmaxf(m0, mx0);
        const float mn1 = fmaxf(m1, mx1);
        const float al0 = __expf(m0 - mn0);
        const float al1 = __expf(m1 - mn1);
        m0 = mn0; m1 = mn1;

        float sum0 = 0.0f, sum1 = 0.0f;
#pragma unroll
        for (int nt = 0; nt < 8; nt++) {
            s[nt][0] = __expf(s[nt][0] - mn0);
            s[nt][1] = __expf(s[nt][1] - mn0);
            s[nt][2] = __expf(s[nt][2] - mn1);
            s[nt][3] = __expf(s[nt][3] - mn1);
            sum0 += s[nt][0] + s[nt][1];
            sum1 += s[nt][2] + s[nt][3];
        }
#pragma unroll
        for (int w = 1; w <= 2; w <<= 1) {
            sum0 += __shfl_xor_sync(0xffffffffu, sum0, w);
            sum1 += __shfl_xor_sync(0xffffffffu, sum1, w);
        }
        l0 = l0 * al0 + sum0;
        l1 = l1 * al1 + sum1;
#pragma unroll
        for (int nt = 0; nt < 16; nt++) {
            o[nt][0] *= al0; o[nt][1] *= al0;
            o[nt][2] *= al1; o[nt][3] *= al1;
        }

        // ---- O += P V : S-fragment -> A-fragment via intra-quad shuffles ----
#pragma unroll
        for (int g = 0; g < 8; g++) {
            const float t0 = __shfl_sync(0xffffffffu, s[g][0], shsrc);
            const float t1 = __shfl_sync(0xffffffffu, s[g][1], shsrc);
            const float t2 = __shfl_sync(0xffffffffu, s[g][2], shsrc);
            const float t3 = __shfl_sync(0xffffffffu, s[g][3], shsrc);
            const float u0 = __shfl_sync(0xffffffffu, s[g][0], shsrc2);
            const float u1 = __shfl_sync(0xffffffffu, s[g][1], shsrc2);
            const float u2 = __shfl_sync(0xffffffffu, s[g][2], shsrc2);
            const float u3 = __shfl_sync(0xffffffffu, s[g][3], shsrc2);
            uint32_t a[4];
            a[0] = f2tf(odd ? t1 : t0);
            a[1] = f2tf(odd ? t3 : t2);
            a[2] = f2tf(odd ? u1 : u0);
            a[3] = f2tf(odd ? u3 : u2);
            const int kb = g * 8;
#pragma unroll
            for (int nt = 0; nt < 16; nt++) {
                uint32_t b[2];
                const int d = nt * 8 + gid;
                b[0] = Vsb[(kb + tig) * FA_VST + d];
                b[1] = Vsb[(kb + tig + 4) * FA_VST + d];
                mma_tf32(o[nt], a, b);
            }
        }
    }

    // ---- normalize + write (merge heads) ----
    const float inv0 = 1.0f / l0;
    const float inv1 = 1.0f / l1;
    float* out0 = Og + (size_t)(q0 + r0) * HID + hoff;
    float* out1 = Og + (size_t)(q0 + r1) * HID + hoff;
#pragma unroll
    for (int nt = 0; nt < 16; nt++) {
        const int d = nt * 8 + tig * 2;
        *(float2*)(out0 + d) = make_float2(o[nt][0] * inv0, o[nt][1] * inv0);
        *(float2*)(out1 + d) = make_float2(o[nt][2] * inv1, o[nt][3] * inv1);
    }
}

// ---------------------------------------------------------------------------
// Launch
// ---------------------------------------------------------------------------
extern "C" void kernel_launch(void* const* d_in, const int* in_sizes, int n_in,
                              void* d_out, int out_size)
{
    (void)in_sizes; (void)n_in; (void)out_size;
    const float* x    = (const float*)d_in[0];
    const float* mask = (const float*)d_in[1];
    const float* Vw[3] = { (const float*)d_in[2], (const float*)d_in[4], (const float*)d_in[6] };
    const float* Uw[3] = { (const float*)d_in[3], (const float*)d_in[5], (const float*)d_in[7] };
    const float* oW = (const float*)d_in[8];
    const float* ob = (const float*)d_in[9];
    float* out = (float*)d_out;

    void *pT, *pQKV, *pAO;
    cudaGetSymbolAddress(&pT, g_T);
    cudaGetSymbolAddress(&pQKV, g_QKV);
    cudaGetSymbolAddress(&pAO, g_AO);
    float* T   = (float*)pT;
    float* QKV = (float*)pQKV;
    float* AO  = (float*)pAO;

    cudaFuncSetAttribute(gemm_tf32_nt, cudaFuncAttributeMaxDynamicSharedMemorySize,
                         GEMM_SMEM_BYTES);
    cudaFuncSetAttribute(flash_attn_tf32, cudaFuncAttributeMaxDynamicSharedMemorySize,
                         FA_SMEM_BYTES);

    // Stage 1: T_i = X @ V_i^T
    {
        dim3 grid(RNK / BN, SEQ / BM);
        for (int i = 0; i < 3; i++)
            gemm_tf32_nt<<<grid, 256, GEMM_SMEM_BYTES>>>(
                x, Vw[i], T + (size_t)i * SEQ * RNK, nullptr, SEQ, RNK, HID);
    }
    // Stage 2: QKV_i = T_i @ U_i^T
    {
        dim3 grid(HID / BN, SEQ / BM);
        for (int i = 0; i < 3; i++)
            gemm_tf32_nt<<<grid, 256, GEMM_SMEM_BYTES>>>(
                T + (size_t)i * SEQ * RNK, Uw[i], QKV + (size_t)i * SEQ * HID,
                nullptr, SEQ, HID, RNK);
    }
    // Stage 3: attention
    {
        dim3 grid(SEQ / 128, NHEAD);
        flash_attn_tf32<<<grid, 256, FA_SMEM_BYTES>>>(
            QKV, QKV + (size_t)SEQ * HID, QKV + (size_t)2 * SEQ * HID, mask, AO);
    }
    // Stage 4: out = AO @ oW^T + ob
    {
        dim3 grid(HID / BN, SEQ / BM);
        gemm_tf32_nt<<<grid, 256, GEMM_SMEM_BYTES>>>(AO, oW, out, ob, SEQ, HID, HID);
    }
}

// round 14
// speedup vs baseline: 4.9867x; 1.0091x over previous
#include <cuda_runtime.h>
#include <math.h>
#include <stdint.h>

// Problem constants
#define SEQ   4096
#define HID   2048
#define RNK   1024
#define NHEAD 16
#define DHEAD 128

// Scratch (device globals: allocation-free per harness rules)
__device__ float g_T[3 * SEQ * RNK];     // low-rank intermediates (k-permuted cols)
__device__ float g_QKV[3 * SEQ * HID];   // Q,K,V (d-permuted cols)
__device__ float g_AO[SEQ * HID];        // attention out (d-permuted cols)
__device__ float g_Xp[SEQ * HID];        // X, k-permuted
__device__ float g_Wp[3 * RNK * HID];    // q/k/v_V weights, k-permuted
__device__ float g_Up[3 * HID * RNK];    // q/k/v_U weights, k-permuted
__device__ float g_Op[HID * HID];        // o_W, k-permuted

__device__ __forceinline__ uint32_t f2tf(float x) {
    uint32_t r;
    asm("cvt.rna.tf32.f32 %0, %1;" : "=r"(r) : "f"(x));
    return r;
}
__device__ __forceinline__ float ex2f(float x) {
    float r;
    asm("ex2.approx.f32 %0, %1;" : "=f"(r) : "f"(x));
    return r;
}
__device__ __forceinline__ void mma_tf32(float* d, const uint32_t* a, const uint32_t* b) {
    asm volatile(
        "mma.sync.aligned.m16n8k8.row.col.f32.tf32.tf32.f32 "
        "{%0,%1,%2,%3}, {%4,%5,%6,%7}, {%8,%9}, {%0,%1,%2,%3};\n"
        : "+f"(d[0]), "+f"(d[1]), "+f"(d[2]), "+f"(d[3])
        : "r"(a[0]), "r"(a[1]), "r"(a[2]), "r"(a[3]),
          "r"(b[0]), "r"(b[1]));
}
__device__ __forceinline__ uint32_t smem_u32(const void* p) {
    return (uint32_t)__cvta_generic_to_shared(p);
}
__device__ __forceinline__ void cp_async16(uint32_t s, const void* g) {
    asm volatile("cp.async.cg.shared.global [%0], [%1], 16;\n"
                 :: "r"(s), "l"(g) : "memory");
}
__device__ __forceinline__ void cp_commit() {
    asm volatile("cp.async.commit_group;\n" ::: "memory");
}
template<int N> __device__ __forceinline__ void cp_wait() {
    asm volatile("cp.async.wait_group %0;\n" :: "n"(N) : "memory");
}

// ===========================================================================
// Pre-pass: permute contiguous dim within groups of 8.
// dst[g*8+j] = src[g*8 + q(j)], q = [0,4,1,5,2,6,3,7]  -> positions (2t,2t+1)
// hold logical k = (t, t+4), enabling LDS.64 fragment pair loads.
// ===========================================================================
__global__ void permute_k8(const float* __restrict__ src, float* __restrict__ dst, int n8)
{
    int i = blockIdx.x * blockDim.x + threadIdx.x;
    if (i >= n8) return;
    const float4* s = (const float4*)(src + (size_t)i * 8);
    float4 u0 = s[0], u1 = s[1];
    float4* d = (float4*)(dst + (size_t)i * 8);
    d[0] = make_float4(u0.x, u1.x, u0.y, u1.y);
    d[1] = make_float4(u0.z, u1.z, u0.w, u1.w);
}

// ===========================================================================
// TF32 GEMM (NT) on k-permuted inputs, cp.async double-buffered.
// C = A[M,K] * B[N,K]^T (+bias).  Tile 128x128x32, warp tile 32x64.
// Fragment loads are LDS.64 (12 per warp-BK vs 24 before).
// permuted_out: write C columns in permuted order (for downstream k-reads).
// ===========================================================================
#define BM 128
#define BN 128
#define BK 32
#define KST 40   // 8 mod 32: LDS.64 banks 8*(r%4)+2*tig all-distinct per phase
#define GEMM_SMEM_BYTES (4 * BM * KST * 4)

__global__ __launch_bounds__(256, 2)
void gemm_tf32_nt(const float* __restrict__ A, const float* __restrict__ B,
                  float* __restrict__ C, const float* __restrict__ bias,
                  int M, int N, int K, int permuted_out)
{
    extern __shared__ uint32_t dyn[];
    uint32_t* AsBase = dyn;
    uint32_t* BsBase = dyn + 2 * BM * KST;

    const int tid  = threadIdx.x;
    const int lane = tid & 31;
    const int warp = tid >> 5;
    const int gid  = lane >> 2;
    const int tig  = lane & 3;
    const int wm   = warp & 3;
    const int wn   = warp >> 2;
    const int m0   = blockIdx.y * BM;
    const int n0   = blockIdx.x * BN;
    const int NT   = K / BK;

    const int lm = tid >> 3;
    const int lk = (tid & 7) << 2;

    float acc[2][8][4];
#pragma unroll
    for (int mt = 0; mt < 2; mt++)
#pragma unroll
        for (int nt = 0; nt < 8; nt++)
#pragma unroll
            for (int r = 0; r < 4; r++) acc[mt][nt][r] = 0.0f;

    {
#pragma unroll
        for (int it = 0; it < 4; it++) {
            const int m = lm + it * 32;
            cp_async16(smem_u32(&AsBase[m * KST + lk]), A + (size_t)(m0 + m) * K + lk);
            cp_async16(smem_u32(&BsBase[m * KST + lk]), B + (size_t)(n0 + m) * K + lk);
        }
        cp_commit();
    }

    for (int j = 0; j < NT; j++) {
        const int buf = j & 1;
        __syncthreads();
        if (j + 1 < NT) {
            const int k0 = (j + 1) * BK;
            uint32_t* An = AsBase + (buf ^ 1) * BM * KST;
            uint32_t* Bn = BsBase + (buf ^ 1) * BN * KST;
#pragma unroll
            for (int it = 0; it < 4; it++) {
                const int m = lm + it * 32;
                cp_async16(smem_u32(&An[m * KST + lk]), A + (size_t)(m0 + m) * K + k0 + lk);
                cp_async16(smem_u32(&Bn[m * KST + lk]), B + (size_t)(n0 + m) * K + k0 + lk);
            }
            cp_commit();
            cp_wait<1>();
        } else {
            cp_wait<0>();
        }
        __syncthreads();

        const uint32_t* As = AsBase + buf * BM * KST;
        const uint32_t* Bs = BsBase + buf * BN * KST;
#pragma unroll
        for (int kb = 0; kb < BK; kb += 8) {
            uint32_t a[2][4], b[8][2];
#pragma unroll
            for (int mt = 0; mt < 2; mt++) {
                const int r = wm * 32 + mt * 16 + gid;
                uint2 x0 = *(const uint2*)&As[r * KST + kb + 2 * tig];
                uint2 x1 = *(const uint2*)&As[(r + 8) * KST + kb + 2 * tig];
                a[mt][0] = x0.x; a[mt][1] = x1.x; a[mt][2] = x0.y; a[mt][3] = x1.y;
            }
#pragma unroll
            for (int nt = 0; nt < 8; nt++) {
                const int c = wn * 64 + nt * 8 + gid;
                uint2 y = *(const uint2*)&Bs[c * KST + kb + 2 * tig];
                b[nt][0] = y.x; b[nt][1] = y.y;
            }
#pragma unroll
            for (int mt = 0; mt < 2; mt++)
#pragma unroll
                for (int nt = 0; nt < 8; nt++)
                    mma_tf32(acc[mt][nt], a[mt], b[nt]);
        }
    }

    // epilogue: logical cols 2tig,2tig+1 -> permuted positions pc0,pc0+2
    const int pc0 = (tig < 2) ? 4 * tig : 4 * tig - 7;
#pragma unroll
    for (int mt = 0; mt < 2; mt++) {
        const int row = m0 + wm * 32 + mt * 16 + gid;
#pragma unroll
        for (int nt = 0; nt < 8; nt++) {
            const int colb = n0 + wn * 64 + nt * 8;
            if (permuted_out) {
                C[(size_t)row * N + colb + pc0]           = acc[mt][nt][0];
                C[(size_t)row * N + colb + pc0 + 2]       = acc[mt][nt][1];
                C[(size_t)(row + 8) * N + colb + pc0]     = acc[mt][nt][2];
                C[(size_t)(row + 8) * N + colb + pc0 + 2] = acc[mt][nt][3];
            } else {
                const int col = colb + tig * 2;
                const float b0 = bias ? bias[col] : 0.0f;
                const float b1 = bias ? bias[col + 1] : 0.0f;
                *(float2*)(C + (size_t)row * N + col) =
                    make_float2(acc[mt][nt][0] + b0, acc[mt][nt][1] + b1);
                *(float2*)(C + (size_t)(row + 8) * N + col) =
                    make_float2(acc[mt][nt][2] + b0, acc[mt][nt][3] + b1);
            }
        }
    }
}

// ===========================================================================
// TF32 flash attention on d-permuted Q/K/V, cp.async double-buffered K/V,
// shuffle-P, LDS.64 S-phase fragments, base-2 softmax, vote-skipped rescale.
// Block = 1 head x 128 queries, 8 warps.  Smem = 384*136*4 = 208896 B.
// ===========================================================================
#define FA_ST 136   // 8 mod 32
#define FA_SMEM_U32 ((128 + 2 * 64 + 2 * 64) * FA_ST)
#define FA_SMEM_BYTES (FA_SMEM_U32 * 4)
#define FA_NT (SEQ / 64)

__global__ __launch_bounds__(256, 1)
void flash_attn_tf32(const float* __restrict__ Qg, const float* __restrict__ Kg,
                     const float* __restrict__ Vg, const float* __restrict__ mask,
                     float* __restrict__ Og)
{
    extern __shared__ uint32_t sm[];
    uint32_t* Qs  = sm;                        // [128][136]
    uint32_t* Ks0 = Qs + 128 * FA_ST;          // [2][64][136]
    uint32_t* Vs0 = Ks0 + 2 * 64 * FA_ST;      // [2][64][136]

    const int tid  = threadIdx.x;
    const int lane = tid & 31;
    const int warp = tid >> 5;
    const int gid  = lane >> 2;
    const int tig  = lane & 3;
    const int h    = blockIdx.y;
    const int q0   = blockIdx.x * 128;
    const int hoff = h * DHEAD;
    const float LOG2E  = 1.4426950408889634f;
    const float scale2 = 0.08838834764831845f * 1.4426950408889634f;  // /sqrt(128)*log2e

    const int krow = tid >> 5;
    const int kc4  = (tid & 31) << 2;

    {
#pragma unroll
        for (int t = 0; t < 8; t++) {
            const int row = krow + t * 8;
            cp_async16(smem_u32(&Ks0[row * FA_ST + kc4]), Kg + (size_t)row * HID + hoff + kc4);
            cp_async16(smem_u32(&Vs0[row * FA_ST + kc4]), Vg + (size_t)row * HID + hoff + kc4);
        }
        cp_commit();
    }
#pragma unroll
    for (int t = 0; t < 16; t++) {
        const int idx = tid + t * 256;
        const int row = idx >> 5;
        const int c4  = (idx & 31) << 2;
        float4 v = *(const float4*)&Qg[(size_t)(q0 + row) * HID + hoff + c4];
        *(uint4*)&Qs[row * FA_ST + c4] =
            make_uint4(f2tf(v.x), f2tf(v.y), f2tf(v.z), f2tf(v.w));
    }

    const int r0 = warp * 16 + gid;
    const int r1 = r0 + 8;
    const float* mbase0 = mask + (size_t)(q0 + r0) * SEQ;
    const float* mbase1 = mask + (size_t)(q0 + r1) * SEQ;
    const int shsrc  = (lane & 28) | (tig >> 1);
    const int shsrc2 = shsrc + 2;
    const bool odd = tig & 1;
    const int pg = (gid < 4) ? 2 * gid : 2 * gid - 7;  // permuted pos of logical d-lane

    float m0 = -INFINITY, m1 = -INFINITY, l0 = 0.0f, l1 = 0.0f;
    float o[16][4];
#pragma unroll
    for (int nt = 0; nt < 16; nt++)
#pragma unroll
        for (int r = 0; r < 4; r++) o[nt][r] = 0.0f;

    for (int j = 0; j < FA_NT; j++) {
        const int buf = j & 1;
        const int j0  = j * 64;
        __syncthreads();
        if (j + 1 < FA_NT) {
            const int jn = (j + 1) * 64;
            uint32_t* Kn = Ks0 + (buf ^ 1) * 64 * FA_ST;
            uint32_t* Vn = Vs0 + (buf ^ 1) * 64 * FA_ST;
#pragma unroll
            for (int t = 0; t < 8; t++) {
                const int row = krow + t * 8;
                cp_async16(smem_u32(&Kn[row * FA_ST + kc4]),
                           Kg + (size_t)(jn + row) * HID + hoff + kc4);
                cp_async16(smem_u32(&Vn[row * FA_ST + kc4]),
                           Vg + (size_t)(jn + row) * HID + hoff + kc4);
            }
            cp_commit();
        }
        // mask prefetch, pre-scaled to base-2 domain
        float2 mk0[8], mk1[8];
#pragma unroll
        for (int nt = 0; nt < 8; nt++) {
            const int c = j0 + nt * 8 + tig * 2;
            mk0[nt] = *(const float2*)(mbase0 + c);
            mk1[nt] = *(const float2*)(mbase1 + c);
            mk0[nt].x *= LOG2E; mk0[nt].y *= LOG2E;
            mk1[nt].x *= LOG2E; mk1[nt].y *= LOG2E;
        }
        if (j + 1 < FA_NT) cp_wait<1>(); else cp_wait<0>();
        __syncthreads();

        const uint32_t* Ksb = Ks0 + buf * 64 * FA_ST;
        const uint32_t* Vsb = Vs0 + buf * 64 * FA_ST;

        // ---- S = Q K^T (LDS.64 fragments) ----
        float s[8][4];
#pragma unroll
        for (int nt = 0; nt < 8; nt++)
#pragma unroll
            for (int r = 0; r < 4; r++) s[nt][r] = 0.0f;
#pragma unroll
        for (int kb = 0; kb < 128; kb += 8) {
            uint2 qa = *(const uint2*)&Qs[r0 * FA_ST + kb + 2 * tig];
            uint2 qb = *(const uint2*)&Qs[r1 * FA_ST + kb + 2 * tig];
            uint32_t a[4] = { qa.x, qb.x, qa.y, qb.y };
#pragma unroll
            for (int nt = 0; nt < 8; nt++) {
                const int c = nt * 8 + gid;
                uint2 kv = *(const uint2*)&Ksb[c * FA_ST + kb + 2 * tig];
                uint32_t b[2] = { kv.x, kv.y };
                mma_tf32(s[nt], a, b);
            }
        }

        // ---- scale + mask (base-2 domain) ----
#pragma unroll
        for (int nt = 0; nt < 8; nt++) {
            s[nt][0] = s[nt][0] * scale2 + mk0[nt].x;
            s[nt][1] = s[nt][1] * scale2 + mk0[nt].y;
            s[nt][2] = s[nt][2] * scale2 + mk1[nt].x;
            s[nt][3] = s[nt][3] * scale2 + mk1[nt].y;
        }

        // ---- online softmax ----
        float mx0 = -INFINITY, mx1 = -INFINITY;
#pragma unroll
        for (int nt = 0; nt < 8; nt++) {
            mx0 = fmaxf(mx0, fmaxf(s[nt][0], s[nt][1]));
            mx1 = fmaxf(mx1, fmaxf(s[nt][2], s[nt][3]));
        }
#pragma unroll
        for (int w = 1; w <= 2; w <<= 1) {
            mx0 = fmaxf(mx0, __shfl_xor_sync(0xffffffffu, mx0, w));
            mx1 = fmaxf(mx1, __shfl_xor_sync(0xffffffffu, mx1, w));
        }
        const float mn0 = fmaxf(m0, mx0);
        const float mn1 = fmaxf(m1, mx1);
        const float al0 = ex2f(m0 - mn0);
        const float al1 = ex2f(m1 - mn1);
        m0 = mn0; m1 = mn1;

        float sum0 = 0.0f, sum1 = 0.0f;
#pragma unroll
        for (int nt = 0; nt < 8; nt++) {
            s[nt][0] = ex2f(s[nt][0] - mn0);
            s[nt][1] = ex2f(s[nt][1] - mn0);
            s[nt][2] = ex2f(s[nt][2] - mn1);
            s[nt][3] = ex2f(s[nt][3] - mn1);
            sum0 += s[nt][0] + s[nt][1];
            sum1 += s[nt][2] + s[nt][3];
        }
#pragma unroll
        for (int w = 1; w <= 2; w <<= 1) {
            sum0 += __shfl_xor_sync(0xffffffffu, sum0, w);
            sum1 += __shfl_xor_sync(0xffffffffu, sum1, w);
        }
        l0 = l0 * al0 + sum0;
        l1 = l1 * al1 + sum1;

        // rescale O only if some row's max moved (warp-uniform vote)
        const bool need = (al0 != 1.0f) || (al1 != 1.0f);
        if (__ballot_sync(0xffffffffu, need)) {
#pragma unroll
            for (int nt = 0; nt < 16; nt++) {
                o[nt][0] *= al0; o[nt][1] *= al0;
                o[nt][2] *= al1; o[nt][3] *= al1;
            }
        }

        // ---- O += P V (shuffle S->A fragment; V d-index permuted via pg) ----
#pragma unroll
        for (int g = 0; g < 8; g++) {
            const float t0 = __shfl_sync(0xffffffffu, s[g][0], shsrc);
            const float t1 = __shfl_sync(0xffffffffu, s[g][1], shsrc);
            const float t2 = __shfl_sync(0xffffffffu, s[g][2], shsrc);
            const float t3 = __shfl_sync(0xffffffffu, s[g][3], shsrc);
            const float u0 = __shfl_sync(0xffffffffu, s[g][0], shsrc2);
            const float u1 = __shfl_sync(0xffffffffu, s[g][1], shsrc2);
            const float u2 = __shfl_sync(0xffffffffu, s[g][2], shsrc2);
            const float u3 = __shfl_sync(0xffffffffu, s[g][3], shsrc2);
            uint32_t a[4];
            a[0] = f2tf(odd ? t1 : t0);
            a[1] = f2tf(odd ? t3 : t2);
            a[2] = f2tf(odd ? u1 : u0);
            a[3] = f2tf(odd ? u3 : u2);
            const int kb = g * 8;
#pragma unroll
            for (int nt = 0; nt < 16; nt++) {
                uint32_t b[2];
                const int d = nt * 8 + pg;
                b[0] = Vsb[(kb + tig) * FA_ST + d];
                b[1] = Vsb[(kb + tig + 4) * FA_ST + d];
                mma_tf32(o[nt], a, b);
            }
        }
    }

    // ---- normalize + write AO with permuted d-columns ----
    const float inv0 = 1.0f / l0;
    const float inv1 = 1.0f / l1;
    const int pc0 = (tig < 2) ? 4 * tig : 4 * tig - 7;
    float* out0 = Og + (size_t)(q0 + r0) * HID + hoff;
    float* out1 = Og + (size_t)(q0 + r1) * HID + hoff;
#pragma unroll
    for (int nt = 0; nt < 16; nt++) {
        const int D = nt * 8;
        out0[D + pc0]     = o[nt][0] * inv0;
        out0[D + pc0 + 2] = o[nt][1] * inv0;
        out1[D + pc0]     = o[nt][2] * inv1;
        out1[D + pc0 + 2] = o[nt][3] * inv1;
    }
}

// ---------------------------------------------------------------------------
// Launch: permute inputs -> 3x(XV^T) -> 3x(TU^T) -> attention -> O-proj
// ---------------------------------------------------------------------------
extern "C" void kernel_launch(void* const* d_in, const int* in_sizes, int n_in,
                              void* d_out, int out_size)
{
    (void)in_sizes; (void)n_in; (void)out_size;
    const float* x    = (const float*)d_in[0];
    const float* mask = (const float*)d_in[1];
    const float* Vw[3] = { (const float*)d_in[2], (const float*)d_in[4], (const float*)d_in[6] };
    const float* Uw[3] = { (const float*)d_in[3], (const float*)d_in[5], (const float*)d_in[7] };
    const float* oW = (const float*)d_in[8];
    const float* ob = (const float*)d_in[9];
    float* out = (float*)d_out;

    void *pT, *pQKV, *pAO, *pXp, *pWp, *pUp, *pOp;
    cudaGetSymbolAddress(&pT, g_T);
    cudaGetSymbolAddress(&pQKV, g_QKV);
    cudaGetSymbolAddress(&pAO, g_AO);
    cudaGetSymbolAddress(&pXp, g_Xp);
    cudaGetSymbolAddress(&pWp, g_Wp);
    cudaGetSymbolAddress(&pUp, g_Up);
    cudaGetSymbolAddress(&pOp, g_Op);
    float* T   = (float*)pT;
    float* QKV = (float*)pQKV;
    float* AO  = (float*)pAO;
    float* Xp  = (float*)pXp;
    float* Wp  = (float*)pWp;
    float* Up  = (float*)pUp;
    float* Op  = (float*)pOp;

    cudaFuncSetAttribute(gemm_tf32_nt, cudaFuncAttributeMaxDynamicSharedMemorySize,
                         GEMM_SMEM_BYTES);
    cudaFuncSetAttribute(flash_attn_tf32, cudaFuncAttributeMaxDynamicSharedMemorySize,
                         FA_SMEM_BYTES);

    // Pre-pass: k-permute X and all weights
    {
        const int TPB = 256;
        int n8x = SEQ * HID / 8;
        permute_k8<<<(n8x + TPB - 1) / TPB, TPB>>>(x, Xp, n8x);
        int n8w = RNK * HID / 8;
        for (int i = 0; i < 3; i++) {
            permute_k8<<<(n8w + TPB - 1) / TPB, TPB>>>(Vw[i], Wp + (size_t)i * RNK * HID, n8w);
            permute_k8<<<(n8w + TPB - 1) / TPB, TPB>>>(Uw[i], Up + (size_t)i * HID * RNK, n8w);
        }
        int n8o = HID * HID / 8;
        permute_k8<<<(n8o + TPB - 1) / TPB, TPB>>>(oW, Op, n8o);
    }

    // Stage 1: T_i = Xp @ Vwp_i^T  (output k-permuted for stage 2)
    {
        dim3 grid(RNK / BN, SEQ / BM);
        for (int i = 0; i < 3; i++)
            gemm_tf32_nt<<<grid, 256, GEMM_SMEM_BYTES>>>(
                Xp, Wp + (size_t)i * RNK * HID, T + (size_t)i * SEQ * RNK,
                nullptr, SEQ, RNK, HID, 1);
    }
    // Stage 2: QKV_i = T_i @ Uwp_i^T  (output d-permuted for attention)
    {
        dim3 grid(HID / BN, SEQ / BM);
        for (int i = 0; i < 3; i++)
            gemm_tf32_nt<<<grid, 256, GEMM_SMEM_BYTES>>>(
                T + (size_t)i * SEQ * RNK, Up + (size_t)i * HID * RNK,
                QKV + (size_t)i * SEQ * HID, nullptr, SEQ, HID, RNK, 1);
    }
    // Stage 3: attention (AO written d-permuted for stage 4)
    {
        dim3 grid(SEQ / 128, NHEAD);
        flash_attn_tf32<<<grid, 256, FA_SMEM_BYTES>>>(
            QKV, QKV + (size_t)SEQ * HID, QKV + (size_t)2 * SEQ * HID, mask, AO);
    }
    // Stage 4: out = AO @ oWp^T + ob  (normal layout output)
    {
        dim3 grid(HID / BN, SEQ / BM);
        gemm_tf32_nt<<<grid, 256, GEMM_SMEM_BYTES>>>(AO, Op, out, ob, SEQ, HID, HID, 0);
    }
}

// round 15
// speedup vs baseline: 4.9895x; 1.0006x over previous
#include <cuda_runtime.h>
#include <math.h>
#include <stdint.h>

// Problem constants
#define SEQ   4096
#define HID   2048
#define RNK   1024
#define NHEAD 16
#define DHEAD 128

// Scratch (device globals: allocation-free per harness rules)
__device__ float g_T[3 * SEQ * RNK];     // low-rank intermediates (k-permuted cols)
__device__ float g_QKV[3 * SEQ * HID];   // Q,K,V (d-permuted cols)
__device__ float g_AO[SEQ * HID];        // attention out (d-permuted cols)
__device__ float g_Xp[SEQ * HID];        // X, k-permuted
__device__ float g_Wp[3 * RNK * HID];    // q/k/v_V weights, k-permuted
__device__ float g_Up[3 * HID * RNK];    // q/k/v_U weights, k-permuted
__device__ float g_Op[HID * HID];        // o_W, k-permuted

__device__ __forceinline__ uint32_t f2tf(float x) {
    uint32_t r;
    asm("cvt.rna.tf32.f32 %0, %1;" : "=r"(r) : "f"(x));
    return r;
}
__device__ __forceinline__ float ex2f(float x) {
    float r;
    asm("ex2.approx.f32 %0, %1;" : "=f"(r) : "f"(x));
    return r;
}
__device__ __forceinline__ void mma_tf32(float* d, const uint32_t* a, const uint32_t* b) {
    asm volatile(
        "mma.sync.aligned.m16n8k8.row.col.f32.tf32.tf32.f32 "
        "{%0,%1,%2,%3}, {%4,%5,%6,%7}, {%8,%9}, {%0,%1,%2,%3};\n"
        : "+f"(d[0]), "+f"(d[1]), "+f"(d[2]), "+f"(d[3])
        : "r"(a[0]), "r"(a[1]), "r"(a[2]), "r"(a[3]),
          "r"(b[0]), "r"(b[1]));
}
__device__ __forceinline__ uint32_t smem_u32(const void* p) {
    return (uint32_t)__cvta_generic_to_shared(p);
}
__device__ __forceinline__ void cp_async16(uint32_t s, const void* g) {
    asm volatile("cp.async.cg.shared.global [%0], [%1], 16;\n"
                 :: "r"(s), "l"(g) : "memory");
}
__device__ __forceinline__ void cp_commit() {
    asm volatile("cp.async.commit_group;\n" ::: "memory");
}
template<int N> __device__ __forceinline__ void cp_wait() {
    asm volatile("cp.async.wait_group %0;\n" :: "n"(N) : "memory");
}

// ===========================================================================
// Pre-pass: permute contiguous dim within groups of 8.
// dst[g*8+j] = src[g*8 + q(j)], q = [0,4,1,5,2,6,3,7]  -> positions (2t,2t+1)
// hold logical k = (t, t+4), enabling LDS.64 fragment pair loads.
// ===========================================================================
__global__ void permute_k8(const float* __restrict__ src, float* __restrict__ dst, int n8)
{
    int i = blockIdx.x * blockDim.x + threadIdx.x;
    if (i >= n8) return;
    const float4* s = (const float4*)(src + (size_t)i * 8);
    float4 u0 = s[0], u1 = s[1];
    float4* d = (float4*)(dst + (size_t)i * 8);
    d[0] = make_float4(u0.x, u1.x, u0.y, u1.y);
    d[1] = make_float4(u0.z, u1.z, u0.w, u1.w);
}

// ===========================================================================
// TF32 GEMM (NT) on k-permuted inputs, cp.async double-buffered.
// C = A[M,K] * B[N,K]^T (+bias).  Tile 128x128x32, warp tile 32x64.
// Fragment loads are LDS.64 (12 per warp-BK vs 24 before).
// permuted_out: write C columns in permuted order (for downstream k-reads).
// ===========================================================================
#define BM 128
#define BN 128
#define BK 32
#define KST 40   // 8 mod 32: LDS.64 banks 8*(r%4)+2*tig all-distinct per phase
#define GEMM_SMEM_BYTES (4 * BM * KST * 4)

__global__ __launch_bounds__(256, 2)
void gemm_tf32_nt(const float* __restrict__ A, const float* __restrict__ B,
                  float* __restrict__ C, const float* __restrict__ bias,
                  int M, int N, int K, int permuted_out)
{
    extern __shared__ uint32_t dyn[];
    uint32_t* AsBase = dyn;
    uint32_t* BsBase = dyn + 2 * BM * KST;

    const int tid  = threadIdx.x;
    const int lane = tid & 31;
    const int warp = tid >> 5;
    const int gid  = lane >> 2;
    const int tig  = lane & 3;
    const int wm   = warp & 3;
    const int wn   = warp >> 2;
    const int m0   = blockIdx.y * BM;
    const int n0   = blockIdx.x * BN;
    const int NT   = K / BK;

    const int lm = tid >> 3;
    const int lk = (tid & 7) << 2;

    float acc[2][8][4];
#pragma unroll
    for (int mt = 0; mt < 2; mt++)
#pragma unroll
        for (int nt = 0; nt < 8; nt++)
#pragma unroll
            for (int r = 0; r < 4; r++) acc[mt][nt][r] = 0.0f;

    {
#pragma unroll
        for (int it = 0; it < 4; it++) {
            const int m = lm + it * 32;
            cp_async16(smem_u32(&AsBase[m * KST + lk]), A + (size_t)(m0 + m) * K + lk);
            cp_async16(smem_u32(&BsBase[m * KST + lk]), B + (size_t)(n0 + m) * K + lk);
        }
        cp_commit();
    }

    for (int j = 0; j < NT; j++) {
        const int buf = j & 1;
        __syncthreads();
        if (j + 1 < NT) {
            const int k0 = (j + 1) * BK;
            uint32_t* An = AsBase + (buf ^ 1) * BM * KST;
            uint32_t* Bn = BsBase + (buf ^ 1) * BN * KST;
#pragma unroll
            for (int it = 0; it < 4; it++) {
                const int m = lm + it * 32;
                cp_async16(smem_u32(&An[m * KST + lk]), A + (size_t)(m0 + m) * K + k0 + lk);
                cp_async16(smem_u32(&Bn[m * KST + lk]), B + (size_t)(n0 + m) * K + k0 + lk);
            }
            cp_commit();
            cp_wait<1>();
        } else {
            cp_wait<0>();
        }
        __syncthreads();

        const uint32_t* As = AsBase + buf * BM * KST;
        const uint32_t* Bs = BsBase + buf * BN * KST;
#pragma unroll
        for (int kb = 0; kb < BK; kb += 8) {
            uint32_t a[2][4], b[8][2];
#pragma unroll
            for (int mt = 0; mt < 2; mt++) {
                const int r = wm * 32 + mt * 16 + gid;
                uint2 x0 = *(const uint2*)&As[r * KST + kb + 2 * tig];
                uint2 x1 = *(const uint2*)&As[(r + 8) * KST + kb + 2 * tig];
                a[mt][0] = x0.x; a[mt][1] = x1.x; a[mt][2] = x0.y; a[mt][3] = x1.y;
            }
#pragma unroll
            for (int nt = 0; nt < 8; nt++) {
                const int c = wn * 64 + nt * 8 + gid;
                uint2 y = *(const uint2*)&Bs[c * KST + kb + 2 * tig];
                b[nt][0] = y.x; b[nt][1] = y.y;
            }
#pragma unroll
            for (int mt = 0; mt < 2; mt++)
#pragma unroll
                for (int nt = 0; nt < 8; nt++)
                    mma_tf32(acc[mt][nt], a[mt], b[nt]);
        }
    }

    // epilogue: logical cols 2tig,2tig+1 -> permuted positions pc0,pc0+2
    const int pc0 = (tig < 2) ? 4 * tig : 4 * tig - 7;
#pragma unroll
    for (int mt = 0; mt < 2; mt++) {
        const int row = m0 + wm * 32 + mt * 16 + gid;
#pragma unroll
        for (int nt = 0; nt < 8; nt++) {
            const int colb = n0 + wn * 64 + nt * 8;
            if (permuted_out) {
                C[(size_t)row * N + colb + pc0]           = acc[mt][nt][0];
                C[(size_t)row * N + colb + pc0 + 2]       = acc[mt][nt][1];
                C[(size_t)(row + 8) * N + colb + pc0]     = acc[mt][nt][2];
                C[(size_t)(row + 8) * N + colb + pc0 + 2] = acc[mt][nt][3];
            } else {
                const int col = colb + tig * 2;
                const float b0 = bias ? bias[col] : 0.0f;
                const float b1 = bias ? bias[col + 1] : 0.0f;
                *(float2*)(C + (size_t)row * N + col) =
                    make_float2(acc[mt][nt][0] + b0, acc[mt][nt][1] + b1);
                *(float2*)(C + (size_t)(row + 8) * N + col) =
                    make_float2(acc[mt][nt][2] + b0, acc[mt][nt][3] + b1);
            }
        }
    }
}

// ===========================================================================
// TF32 flash attention on d-permuted Q/K/V, cp.async double-buffered K/V,
// shuffle-P, LDS.64 S-phase fragments, base-2 softmax, vote-skipped rescale.
// Block = 1 head x 128 queries, 8 warps.  Smem = 384*136*4 = 208896 B.
// ===========================================================================
#define FA_ST 136   // 8 mod 32
#define FA_SMEM_U32 ((128 + 2 * 64 + 2 * 64) * FA_ST)
#define FA_SMEM_BYTES (FA_SMEM_U32 * 4)
#define FA_NT (SEQ / 64)

__global__ __launch_bounds__(256, 1)
void flash_attn_tf32(const float* __restrict__ Qg, const float* __restrict__ Kg,
                     const float* __restrict__ Vg, const float* __restrict__ mask,
                     float* __restrict__ Og)
{
    extern __shared__ uint32_t sm[];
    uint32_t* Qs  = sm;                        // [128][136]
    uint32_t* Ks0 = Qs + 128 * FA_ST;          // [2][64][136]
    uint32_t* Vs0 = Ks0 + 2 * 64 * FA_ST;      // [2][64][136]

    const int tid  = threadIdx.x;
    const int lane = tid & 31;
    const int warp = tid >> 5;
    const int gid  = lane >> 2;
    const int tig  = lane & 3;
    const int h    = blockIdx.y;
    const int q0   = blockIdx.x * 128;
    const int hoff = h * DHEAD;
    const float LOG2E  = 1.4426950408889634f;
    const float scale2 = 0.08838834764831845f * 1.4426950408889634f;  // /sqrt(128)*log2e

    const int krow = tid >> 5;
    const int kc4  = (tid & 31) << 2;

    {
#pragma unroll
        for (int t = 0; t < 8; t++) {
            const int row = krow + t * 8;
            cp_async16(smem_u32(&Ks0[row * FA_ST + kc4]), Kg + (size_t)row * HID + hoff + kc4);
            cp_async16(smem_u32(&Vs0[row * FA_ST + kc4]), Vg + (size_t)row * HID + hoff + kc4);
        }
        cp_commit();
    }
#pragma unroll
    for (int t = 0; t < 16; t++) {
        const int idx = tid + t * 256;
        const int row = idx >> 5;
        const int c4  = (idx & 31) << 2;
        float4 v = *(const float4*)&Qg[(size_t)(q0 + row) * HID + hoff + c4];
        *(uint4*)&Qs[row * FA_ST + c4] =
            make_uint4(f2tf(v.x), f2tf(v.y), f2tf(v.z), f2tf(v.w));
    }

    const int r0 = warp * 16 + gid;
    const int r1 = r0 + 8;
    const float* mbase0 = mask + (size_t)(q0 + r0) * SEQ;
    const float* mbase1 = mask + (size_t)(q0 + r1) * SEQ;
    const int shsrc  = (lane & 28) | (tig >> 1);
    const int shsrc2 = shsrc + 2;
    const bool odd = tig & 1;
    const int pg = (gid < 4) ? 2 * gid : 2 * gid - 7;  // permuted pos of logical d-lane

    float m0 = -INFINITY, m1 = -INFINITY, l0 = 0.0f, l1 = 0.0f;
    float o[16][4];
#pragma unroll
    for (int nt = 0; nt < 16; nt++)
#pragma unroll
        for (int r = 0; r < 4; r++) o[nt][r] = 0.0f;

    for (int j = 0; j < FA_NT; j++) {
        const int buf = j & 1;
        const int j0  = j * 64;
        __syncthreads();
        if (j + 1 < FA_NT) {
            const int jn = (j + 1) * 64;
            uint32_t* Kn = Ks0 + (buf ^ 1) * 64 * FA_ST;
            uint32_t* Vn = Vs0 + (buf ^ 1) * 64 * FA_ST;
#pragma unroll
            for (int t = 0; t < 8; t++) {
                const int row = krow + t * 8;
                cp_async16(smem_u32(&Kn[row * FA_ST + kc4]),
                           Kg + (size_t)(jn + row) * HID + hoff + kc4);
                cp_async16(smem_u32(&Vn[row * FA_ST + kc4]),
                           Vg + (size_t)(jn + row) * HID + hoff + kc4);
            }
            cp_commit();
        }
        // mask prefetch, pre-scaled to base-2 domain
        float2 mk0[8], mk1[8];
#pragma unroll
        for (int nt = 0; nt < 8; nt++) {
            const int c = j0 + nt * 8 + tig * 2;
            mk0[nt] = *(const float2*)(mbase0 + c);
            mk1[nt] = *(const float2*)(mbase1 + c);
            mk0[nt].x *= LOG2E; mk0[nt].y *= LOG2E;
            mk1[nt].x *= LOG2E; mk1[nt].y *= LOG2E;
        }
        if (j + 1 < FA_NT) cp_wait<1>(); else cp_wait<0>();
        __syncthreads();

        const uint32_t* Ksb = Ks0 + buf * 64 * FA_ST;
        const uint32_t* Vsb = Vs0 + buf * 64 * FA_ST;

        // ---- S = Q K^T (LDS.64 fragments) ----
        float s[8][4];
#pragma unroll
        for (int nt = 0; nt < 8; nt++)
#pragma unroll
            for (int r = 0; r < 4; r++) s[nt][r] = 0.0f;
#pragma unroll
        for (int kb = 0; kb < 128; kb += 8) {
            uint2 qa = *(const uint2*)&Qs[r0 * FA_ST + kb + 2 * tig];
            uint2 qb = *(const uint2*)&Qs[r1 * FA_ST + kb + 2 * tig];
            uint32_t a[4] = { qa.x, qb.x, qa.y, qb.y };
#pragma unroll
            for (int nt = 0; nt < 8; nt++) {
                const int c = nt * 8 + gid;
                uint2 kv = *(const uint2*)&Ksb[c * FA_ST + kb + 2 * tig];
                uint32_t b[2] = { kv.x, kv.y };
                mma_tf32(s[nt], a, b);
            }
        }

        // ---- scale + mask (base-2 domain) ----
#pragma unroll
        for (int nt = 0; nt < 8; nt++) {
            s[nt][0] = s[nt][0] * scale2 + mk0[nt].x;
            s[nt][1] = s[nt][1] * scale2 + mk0[nt].y;
            s[nt][2] = s[nt][2] * scale2 + mk1[nt].x;
            s[nt][3] = s[nt][3] * scale2 + mk1[nt].y;
        }

        // ---- online softmax ----
        float mx0 = -INFINITY, mx1 = -INFINITY;
#pragma unroll
        for (int nt = 0; nt < 8; nt++) {
            mx0 = fmaxf(mx0, fmaxf(s[nt][0], s[nt][1]));
            mx1 = fmaxf(mx1, fmaxf(s[nt][2], s[nt][3]));
        }
#pragma unroll
        for (int w = 1; w <= 2; w <<= 1) {
            mx0 = fmaxf(mx0, __shfl_xor_sync(0xffffffffu, mx0, w));
            mx1 = fmaxf(mx1, __shfl_xor_sync(0xffffffffu, mx1, w));
        }
        const float mn0 = fmaxf(m0, mx0);
        const float mn1 = fmaxf(m1, mx1);
        const float al0 = ex2f(m0 - mn0);
        const float al1 = ex2f(m1 - mn1);
        m0 = mn0; m1 = mn1;

        float sum0 = 0.0f, sum1 = 0.0f;
#pragma unroll
        for (int nt = 0; nt < 8; nt++) {
            s[nt][0] = ex2f(s[nt][0] - mn0);
            s[nt][1] = ex2f(s[nt][1] - mn0);
            s[nt][2] = ex2f(s[nt][2] - mn1);
            s[nt][3] = ex2f(s[nt][3] - mn1);
            sum0 += s[nt][0] + s[nt][1];
            sum1 += s[nt][2] + s[nt][3];
        }
#pragma unroll
        for (int w = 1; w <= 2; w <<= 1) {
            sum0 += __shfl_xor_sync(0xffffffffu, sum0, w);
            sum1 += __shfl_xor_sync(0xffffffffu, sum1, w);
        }
        l0 = l0 * al0 + sum0;
        l1 = l1 * al1 + sum1;

        // rescale O only if some row's max moved (warp-uniform vote)
        const bool need = (al0 != 1.0f) || (al1 != 1.0f);
        if (__ballot_sync(0xffffffffu, need)) {
#pragma unroll
            for (int nt = 0; nt < 16; nt++) {
                o[nt][0] *= al0; o[nt][1] *= al0;
                o[nt][2] *= al1; o[nt][3] *= al1;
            }
        }

        // ---- O += P V (shuffle S->A fragment; V d-index permuted via pg) ----
#pragma unroll
        for (int g = 0; g < 8; g++) {
            const float t0 = __shfl_sync(0xffffffffu, s[g][0], shsrc);
            const float t1 = __shfl_sync(0xffffffffu, s[g][1], shsrc);
            const float t2 = __shfl_sync(0xffffffffu, s[g][2], shsrc);
            const float t3 = __shfl_sync(0xffffffffu, s[g][3], shsrc);
            const float u0 = __shfl_sync(0xffffffffu, s[g][0], shsrc2);
            const float u1 = __shfl_sync(0xffffffffu, s[g][1], shsrc2);
            const float u2 = __shfl_sync(0xffffffffu, s[g][2], shsrc2);
            const float u3 = __shfl_sync(0xffffffffu, s[g][3], shsrc2);
            uint32_t a[4];
            a[0] = f2tf(odd ? t1 : t0);
            a[1] = f2tf(odd ? t3 : t2);
            a[2] = f2tf(odd ? u1 : u0);
            a[3] = f2tf(odd ? u3 : u2);
            const int kb = g * 8;
#pragma unroll
            for (int nt = 0; nt < 16; nt++) {
                uint32_t b[2];
                const int d = nt * 8 + pg;
                b[0] = Vsb[(kb + tig) * FA_ST + d];
                b[1] = Vsb[(kb + tig + 4) * FA_ST + d];
                mma_tf32(o[nt], a, b);
            }
        }
    }

    // ---- normalize + write AO with permuted d-columns ----
    const float inv0 = 1.0f / l0;
    const float inv1 = 1.0f / l1;
    const int pc0 = (tig < 2) ? 4 * tig : 4 * tig - 7;
    float* out0 = Og + (size_t)(q0 + r0) * HID + hoff;
    float* out1 = Og + (size_t)(q0 + r1) * HID + hoff;
#pragma unroll
    for (int nt = 0; nt < 16; nt++) {
        const int D = nt * 8;
        out0[D + pc0]     = o[nt][0] * inv0;
        out0[D + pc0 + 2] = o[nt][1] * inv0;
        out1[D + pc0]     = o[nt][2] * inv1;
        out1[D + pc0 + 2] = o[nt][3] * inv1;
    }
}

// ---------------------------------------------------------------------------
// Launch: permute inputs -> 3x(XV^T) -> 3x(TU^T) -> attention -> O-proj
// ---------------------------------------------------------------------------
extern "C" void kernel_launch(void* const* d_in, const int* in_sizes, int n_in,
                              void* d_out, int out_size)
{
    (void)in_sizes; (void)n_in; (void)out_size;
    const float* x    = (const float*)d_in[0];
    const float* mask = (const float*)d_in[1];
    const float* Vw[3] = { (const float*)d_in[2], (const float*)d_in[4], (const float*)d_in[6] };
    const float* Uw[3] = { (const float*)d_in[3], (const float*)d_in[5], (const float*)d_in[7] };
    const float* oW = (const float*)d_in[8];
    const float* ob = (const float*)d_in[9];
    float* out = (float*)d_out;

    void *pT, *pQKV, *pAO, *pXp, *pWp, *pUp, *pOp;
    cudaGetSymbolAddress(&pT, g_T);
    cudaGetSymbolAddress(&pQKV, g_QKV);
    cudaGetSymbolAddress(&pAO, g_AO);
    cudaGetSymbolAddress(&pXp, g_Xp);
    cudaGetSymbolAddress(&pWp, g_Wp);
    cudaGetSymbolAddress(&pUp, g_Up);
    cudaGetSymbolAddress(&pOp, g_Op);
    float* T   = (float*)pT;
    float* QKV = (float*)pQKV;
    float* AO  = (float*)pAO;
    float* Xp  = (float*)pXp;
    float* Wp  = (float*)pWp;
    float* Up  = (float*)pUp;
    float* Op  = (float*)pOp;

    cudaFuncSetAttribute(gemm_tf32_nt, cudaFuncAttributeMaxDynamicSharedMemorySize,
                         GEMM_SMEM_BYTES);
    cudaFuncSetAttribute(flash_attn_tf32, cudaFuncAttributeMaxDynamicSharedMemorySize,
                         FA_SMEM_BYTES);

    // Pre-pass: k-permute X and all weights
    {
        const int TPB = 256;
        int n8x = SEQ * HID / 8;
        permute_k8<<<(n8x + TPB - 1) / TPB, TPB>>>(x, Xp, n8x);
        int n8w = RNK * HID / 8;
        for (int i = 0; i < 3; i++) {
            permute_k8<<<(n8w + TPB - 1) / TPB, TPB>>>(Vw[i], Wp + (size_t)i * RNK * HID, n8w);
            permute_k8<<<(n8w + TPB - 1) / TPB, TPB>>>(Uw[i], Up + (size_t)i * HID * RNK, n8w);
        }
        int n8o = HID * HID / 8;
        permute_k8<<<(n8o + TPB - 1) / TPB, TPB>>>(oW, Op, n8o);
    }

    // Stage 1: T_i = Xp @ Vwp_i^T  (output k-permuted for stage 2)
    {
        dim3 grid(RNK / BN, SEQ / BM);
        for (int i = 0; i < 3; i++)
            gemm_tf32_nt<<<grid, 256, GEMM_SMEM_BYTES>>>(
                Xp, Wp + (size_t)i * RNK * HID, T + (size_t)i * SEQ * RNK,
                nullptr, SEQ, RNK, HID, 1);
    }
    // Stage 2: QKV_i = T_i @ Uwp_i^T  (output d-permuted for attention)
    {
        dim3 grid(HID / BN, SEQ / BM);
        for (int i = 0; i < 3; i++)
            gemm_tf32_nt<<<grid, 256, GEMM_SMEM_BYTES>>>(
                T + (size_t)i * SEQ * RNK, Up + (size_t)i * HID * RNK,
                QKV + (size_t)i * SEQ * HID, nullptr, SEQ, HID, RNK, 1);
    }
    // Stage 3: attention (AO written d-permuted for stage 4)
    {
        dim3 grid(SEQ / 128, NHEAD);
        flash_attn_tf32<<<grid, 256, FA_SMEM_BYTES>>>(
            QKV, QKV + (size_t)SEQ * HID, QKV + (size_t)2 * SEQ * HID, mask, AO);
    }
    // Stage 4: out = AO @ oWp^T + ob  (normal layout output)
    {
        dim3 grid(HID / BN, SEQ / BM);
        gemm_tf32_nt<<<grid, 256, GEMM_SMEM_BYTES>>>(AO, Op, out, ob, SEQ, HID, HID, 0);
    }
}

// round 16
// speedup vs baseline: 5.2852x; 1.0593x over previous
#include <cuda_runtime.h>
#include <math.h>
#include <stdint.h>

// Problem constants
#define SEQ   4096
#define HID   2048
#define RNK   1024
#define NHEAD 16
#define DHEAD 128

// Scratch (device globals: allocation-free per harness rules)
__device__ float g_T[3 * SEQ * RNK];     // low-rank intermediates (k-permuted cols)
__device__ float g_QKV[3 * SEQ * HID];   // Q,K,V (d-permuted cols)
__device__ float g_AO[SEQ * HID];        // attention out (d-permuted cols)
__device__ float g_Xp[SEQ * HID];        // X, k-permuted
__device__ float g_Wp[3 * RNK * HID];    // q/k/v_V weights, k-permuted
__device__ float g_Up[3 * HID * RNK];    // q/k/v_U weights, k-permuted
__device__ float g_Op[HID * HID];        // o_W, k-permuted

__device__ __forceinline__ uint32_t f2tf(float x) {
    uint32_t r;
    asm("cvt.rna.tf32.f32 %0, %1;" : "=r"(r) : "f"(x));
    return r;
}
__device__ __forceinline__ float ex2f(float x) {
    float r;
    asm("ex2.approx.f32 %0, %1;" : "=f"(r) : "f"(x));
    return r;
}
__device__ __forceinline__ void mma_tf32(float* d, const uint32_t* a, const uint32_t* b) {
    asm volatile(
        "mma.sync.aligned.m16n8k8.row.col.f32.tf32.tf32.f32 "
        "{%0,%1,%2,%3}, {%4,%5,%6,%7}, {%8,%9}, {%0,%1,%2,%3};\n"
        : "+f"(d[0]), "+f"(d[1]), "+f"(d[2]), "+f"(d[3])
        : "r"(a[0]), "r"(a[1]), "r"(a[2]), "r"(a[3]),
          "r"(b[0]), "r"(b[1]));
}
__device__ __forceinline__ uint32_t smem_u32(const void* p) {
    return (uint32_t)__cvta_generic_to_shared(p);
}
__device__ __forceinline__ void cp_async16(uint32_t s, const void* g) {
    asm volatile("cp.async.cg.shared.global [%0], [%1], 16;\n"
                 :: "r"(s), "l"(g) : "memory");
}
__device__ __forceinline__ void cp_commit() {
    asm volatile("cp.async.commit_group;\n" ::: "memory");
}
template<int N> __device__ __forceinline__ void cp_wait() {
    asm volatile("cp.async.wait_group %0;\n" :: "n"(N) : "memory");
}

// ===========================================================================
// Pre-pass: permute contiguous dim within groups of 8.
// dst[g*8+j] = src[g*8 + q(j)], q = [0,4,1,5,2,6,3,7]
// ===========================================================================
__global__ void permute_k8(const float* __restrict__ src, float* __restrict__ dst, int n8)
{
    int i = blockIdx.x * blockDim.x + threadIdx.x;
    if (i >= n8) return;
    const float4* s = (const float4*)(src + (size_t)i * 8);
    float4 u0 = s[0], u1 = s[1];
    float4* d = (float4*)(dst + (size_t)i * 8);
    d[0] = make_float4(u0.x, u1.x, u0.y, u1.y);
    d[1] = make_float4(u0.z, u1.z, u0.w, u1.w);
}

// ===========================================================================
// TF32 GEMM (NT) on k-permuted inputs, cp.async double-buffered, batched
// over blockIdx.z (stride-selected A/B/C).  Tile 128x128x32, warp 32x64.
// ===========================================================================
#define BM 128
#define BN 128
#define BK 32
#define KST 40
#define GEMM_SMEM_BYTES (4 * BM * KST * 4)

__global__ __launch_bounds__(256, 2)
void gemm_tf32_nt(const float* __restrict__ A0, const float* __restrict__ B0,
                  float* __restrict__ C0, const float* __restrict__ bias,
                  int M, int N, int K, int permuted_out,
                  size_t strideA, size_t strideB, size_t strideC)
{
    extern __shared__ uint32_t dyn[];
    uint32_t* AsBase = dyn;
    uint32_t* BsBase = dyn + 2 * BM * KST;

    const float* A = A0 + strideA * blockIdx.z;
    const float* B = B0 + strideB * blockIdx.z;
    float*       C = C0 + strideC * blockIdx.z;

    const int tid  = threadIdx.x;
    const int lane = tid & 31;
    const int warp = tid >> 5;
    const int gid  = lane >> 2;
    const int tig  = lane & 3;
    const int wm   = warp & 3;
    const int wn   = warp >> 2;
    const int m0   = blockIdx.y * BM;
    const int n0   = blockIdx.x * BN;
    const int NT   = K / BK;

    const int lm = tid >> 3;
    const int lk = (tid & 7) << 2;

    float acc[2][8][4];
#pragma unroll
    for (int mt = 0; mt < 2; mt++)
#pragma unroll
        for (int nt = 0; nt < 8; nt++)
#pragma unroll
            for (int r = 0; r < 4; r++) acc[mt][nt][r] = 0.0f;

    {
#pragma unroll
        for (int it = 0; it < 4; it++) {
            const int m = lm + it * 32;
            cp_async16(smem_u32(&AsBase[m * KST + lk]), A + (size_t)(m0 + m) * K + lk);
            cp_async16(smem_u32(&BsBase[m * KST + lk]), B + (size_t)(n0 + m) * K + lk);
        }
        cp_commit();
    }

    for (int j = 0; j < NT; j++) {
        const int buf = j & 1;
        __syncthreads();
        if (j + 1 < NT) {
            const int k0 = (j + 1) * BK;
            uint32_t* An = AsBase + (buf ^ 1) * BM * KST;
            uint32_t* Bn = BsBase + (buf ^ 1) * BN * KST;
#pragma unroll
            for (int it = 0; it < 4; it++) {
                const int m = lm + it * 32;
                cp_async16(smem_u32(&An[m * KST + lk]), A + (size_t)(m0 + m) * K + k0 + lk);
                cp_async16(smem_u32(&Bn[m * KST + lk]), B + (size_t)(n0 + m) * K + k0 + lk);
            }
            cp_commit();
            cp_wait<1>();
        } else {
            cp_wait<0>();
        }
        __syncthreads();

        const uint32_t* As = AsBase + buf * BM * KST;
        const uint32_t* Bs = BsBase + buf * BN * KST;
#pragma unroll
        for (int kb = 0; kb < BK; kb += 8) {
            uint32_t a[2][4], b[8][2];
#pragma unroll
            for (int mt = 0; mt < 2; mt++) {
                const int r = wm * 32 + mt * 16 + gid;
                uint2 x0 = *(const uint2*)&As[r * KST + kb + 2 * tig];
                uint2 x1 = *(const uint2*)&As[(r + 8) * KST + kb + 2 * tig];
                a[mt][0] = x0.x; a[mt][1] = x1.x; a[mt][2] = x0.y; a[mt][3] = x1.y;
            }
#pragma unroll
            for (int nt = 0; nt < 8; nt++) {
                const int c = wn * 64 + nt * 8 + gid;
                uint2 y = *(const uint2*)&Bs[c * KST + kb + 2 * tig];
                b[nt][0] = y.x; b[nt][1] = y.y;
            }
#pragma unroll
            for (int mt = 0; mt < 2; mt++)
#pragma unroll
                for (int nt = 0; nt < 8; nt++)
                    mma_tf32(acc[mt][nt], a[mt], b[nt]);
        }
    }

    const int pc0 = (tig < 2) ? 4 * tig : 4 * tig - 7;
#pragma unroll
    for (int mt = 0; mt < 2; mt++) {
        const int row = m0 + wm * 32 + mt * 16 + gid;
#pragma unroll
        for (int nt = 0; nt < 8; nt++) {
            const int colb = n0 + wn * 64 + nt * 8;
            if (permuted_out) {
                C[(size_t)row * N + colb + pc0]           = acc[mt][nt][0];
                C[(size_t)row * N + colb + pc0 + 2]       = acc[mt][nt][1];
                C[(size_t)(row + 8) * N + colb + pc0]     = acc[mt][nt][2];
                C[(size_t)(row + 8) * N + colb + pc0 + 2] = acc[mt][nt][3];
            } else {
                const int col = colb + tig * 2;
                const float b0 = bias ? bias[col] : 0.0f;
                const float b1 = bias ? bias[col + 1] : 0.0f;
                *(float2*)(C + (size_t)row * N + col) =
                    make_float2(acc[mt][nt][0] + b0, acc[mt][nt][1] + b1);
                *(float2*)(C + (size_t)(row + 8) * N + col) =
                    make_float2(acc[mt][nt][2] + b0, acc[mt][nt][3] + b1);
            }
        }
    }
}

// ===========================================================================
// TF32 flash attention, shuffle-free PV via k-slot renaming.
// The mma k-axis order within each 8-key group is chosen as
// kappa(t) = 2t (t<4), 2(t-4)+1 (t>=4): then the S accumulator IS the PV
// A-fragment (a = {c0,c2,c1,c3}) and B is fed from V rows (kb+2tig, +1).
// V stride 132 (=4 mod 32) keeps the new V-load bank map (8*tig+pg) distinct.
// Block = 1 head x 128 queries, 8 warps.  Smem = 206848 B (1 CTA/SM).
// ===========================================================================
#define FA_ST  136   // Q/K stride (8 mod 32, LDS.64 S-phase)
#define FA_VST 132   // V stride (4 mod 32)
#define FA_SMEM_U32 (128 * FA_ST + 2 * 64 * FA_ST + 2 * 64 * FA_VST)
#define FA_SMEM_BYTES (FA_SMEM_U32 * 4)
#define FA_NT (SEQ / 64)

__global__ __launch_bounds__(256, 1)
void flash_attn_tf32(const float* __restrict__ Qg, const float* __restrict__ Kg,
                     const float* __restrict__ Vg, const float* __restrict__ mask,
                     float* __restrict__ Og)
{
    extern __shared__ uint32_t sm[];
    uint32_t* Qs  = sm;                        // [128][136]
    uint32_t* Ks0 = Qs + 128 * FA_ST;          // [2][64][136]
    uint32_t* Vs0 = Ks0 + 2 * 64 * FA_ST;      // [2][64][132]

    const int tid  = threadIdx.x;
    const int lane = tid & 31;
    const int warp = tid >> 5;
    const int gid  = lane >> 2;
    const int tig  = lane & 3;
    const int h    = blockIdx.y;
    const int q0   = blockIdx.x * 128;
    const int hoff = h * DHEAD;
    const float LOG2E  = 1.4426950408889634f;
    const float scale2 = 0.08838834764831845f * 1.4426950408889634f;

    const int krow = tid >> 5;
    const int kc4  = (tid & 31) << 2;

    {
#pragma unroll
        for (int t = 0; t < 8; t++) {
            const int row = krow + t * 8;
            cp_async16(smem_u32(&Ks0[row * FA_ST + kc4]),  Kg + (size_t)row * HID + hoff + kc4);
            cp_async16(smem_u32(&Vs0[row * FA_VST + kc4]), Vg + (size_t)row * HID + hoff + kc4);
        }
        cp_commit();
    }
#pragma unroll
    for (int t = 0; t < 16; t++) {
        const int idx = tid + t * 256;
        const int row = idx >> 5;
        const int c4  = (idx & 31) << 2;
        float4 v = *(const float4*)&Qg[(size_t)(q0 + row) * HID + hoff + c4];
        *(uint4*)&Qs[row * FA_ST + c4] =
            make_uint4(f2tf(v.x), f2tf(v.y), f2tf(v.z), f2tf(v.w));
    }

    const int r0 = warp * 16 + gid;
    const int r1 = r0 + 8;
    const float* mbase0 = mask + (size_t)(q0 + r0) * SEQ;
    const float* mbase1 = mask + (size_t)(q0 + r1) * SEQ;
    const int pg = (gid < 4) ? 2 * gid : 2 * gid - 7;  // permuted pos of logical d-lane

    float m0 = -INFINITY, m1 = -INFINITY, l0 = 0.0f, l1 = 0.0f;
    float o[16][4];
#pragma unroll
    for (int nt = 0; nt < 16; nt++)
#pragma unroll
        for (int r = 0; r < 4; r++) o[nt][r] = 0.0f;

    for (int j = 0; j < FA_NT; j++) {
        const int buf = j & 1;
        const int j0  = j * 64;
        __syncthreads();
        if (j + 1 < FA_NT) {
            const int jn = (j + 1) * 64;
            uint32_t* Kn = Ks0 + (buf ^ 1) * 64 * FA_ST;
            uint32_t* Vn = Vs0 + (buf ^ 1) * 64 * FA_VST;
#pragma unroll
            for (int t = 0; t < 8; t++) {
                const int row = krow + t * 8;
                cp_async16(smem_u32(&Kn[row * FA_ST + kc4]),
                           Kg + (size_t)(jn + row) * HID + hoff + kc4);
                cp_async16(smem_u32(&Vn[row * FA_VST + kc4]),
                           Vg + (size_t)(jn + row) * HID + hoff + kc4);
            }
            cp_commit();
        }
        // mask prefetch, pre-scaled to base-2 domain
        float2 mk0[8], mk1[8];
#pragma unroll
        for (int nt = 0; nt < 8; nt++) {
            const int c = j0 + nt * 8 + tig * 2;
            mk0[nt] = *(const float2*)(mbase0 + c);
            mk1[nt] = *(const float2*)(mbase1 + c);
            mk0[nt].x *= LOG2E; mk0[nt].y *= LOG2E;
            mk1[nt].x *= LOG2E; mk1[nt].y *= LOG2E;
        }
        if (j + 1 < FA_NT) cp_wait<1>(); else cp_wait<0>();
        __syncthreads();

        const uint32_t* Ksb = Ks0 + buf * 64 * FA_ST;
        const uint32_t* Vsb = Vs0 + buf * 64 * FA_VST;

        // ---- S = Q K^T (LDS.64 fragments) ----
        float s[8][4];
#pragma unroll
        for (int nt = 0; nt < 8; nt++)
#pragma unroll
            for (int r = 0; r < 4; r++) s[nt][r] = 0.0f;
#pragma unroll
        for (int kb = 0; kb < 128; kb += 8) {
            uint2 qa = *(const uint2*)&Qs[r0 * FA_ST + kb + 2 * tig];
            uint2 qb = *(const uint2*)&Qs[r1 * FA_ST + kb + 2 * tig];
            uint32_t a[4] = { qa.x, qb.x, qa.y, qb.y };
#pragma unroll
            for (int nt = 0; nt < 8; nt++) {
                const int c = nt * 8 + gid;
                uint2 kv = *(const uint2*)&Ksb[c * FA_ST + kb + 2 * tig];
                uint32_t b[2] = { kv.x, kv.y };
                mma_tf32(s[nt], a, b);
            }
        }

        // ---- scale + mask (base-2 domain) ----
#pragma unroll
        for (int nt = 0; nt < 8; nt++) {
            s[nt][0] = s[nt][0] * scale2 + mk0[nt].x;
            s[nt][1] = s[nt][1] * scale2 + mk0[nt].y;
            s[nt][2] = s[nt][2] * scale2 + mk1[nt].x;
            s[nt][3] = s[nt][3] * scale2 + mk1[nt].y;
        }

        // ---- online softmax ----
        float mx0 = -INFINITY, mx1 = -INFINITY;
#pragma unroll
        for (int nt = 0; nt < 8; nt++) {
            mx0 = fmaxf(mx0, fmaxf(s[nt][0], s[nt][1]));
            mx1 = fmaxf(mx1, fmaxf(s[nt][2], s[nt][3]));
        }
#pragma unroll
        for (int w = 1; w <= 2; w <<= 1) {
            mx0 = fmaxf(mx0, __shfl_xor_sync(0xffffffffu, mx0, w));
            mx1 = fmaxf(mx1, __shfl_xor_sync(0xffffffffu, mx1, w));
        }
        const float mn0 = fmaxf(m0, mx0);
        const float mn1 = fmaxf(m1, mx1);
        const float al0 = ex2f(m0 - mn0);
        const float al1 = ex2f(m1 - mn1);
        m0 = mn0; m1 = mn1;

        float sum0 = 0.0f, sum1 = 0.0f;
#pragma unroll
        for (int nt = 0; nt < 8; nt++) {
            s[nt][0] = ex2f(s[nt][0] - mn0);
            s[nt][1] = ex2f(s[nt][1] - mn0);
            s[nt][2] = ex2f(s[nt][2] - mn1);
            s[nt][3] = ex2f(s[nt][3] - mn1);
            sum0 += s[nt][0] + s[nt][1];
            sum1 += s[nt][2] + s[nt][3];
        }
#pragma unroll
        for (int w = 1; w <= 2; w <<= 1) {
            sum0 += __shfl_xor_sync(0xffffffffu, sum0, w);
            sum1 += __shfl_xor_sync(0xffffffffu, sum1, w);
        }
        l0 = l0 * al0 + sum0;
        l1 = l1 * al1 + sum1;

        const bool need = (al0 != 1.0f) || (al1 != 1.0f);
        if (__ballot_sync(0xffffffffu, need)) {
#pragma unroll
            for (int nt = 0; nt < 16; nt++) {
                o[nt][0] *= al0; o[nt][1] *= al0;
                o[nt][2] *= al1; o[nt][3] *= al1;
            }
        }

        // ---- O += P V : shuffle-free (k-slot renaming kappa) ----
#pragma unroll
        for (int g = 0; g < 8; g++) {
            uint32_t a[4];
            a[0] = f2tf(s[g][0]);   // P(r0, 2tig)   -> slot tig
            a[1] = f2tf(s[g][2]);   // P(r1, 2tig)
            a[2] = f2tf(s[g][1]);   // P(r0, 2tig+1) -> slot tig+4
            a[3] = f2tf(s[g][3]);   // P(r1, 2tig+1)
            const int kb = g * 8;
#pragma unroll
            for (int nt = 0; nt < 16; nt++) {
                uint32_t b[2];
                const int d = nt * 8 + pg;
                b[0] = Vsb[(kb + 2 * tig) * FA_VST + d];       // key kb+2tig
                b[1] = Vsb[(kb + 2 * tig + 1) * FA_VST + d];   // key kb+2tig+1
                mma_tf32(o[nt], a, b);
            }
        }
    }

    // ---- normalize + write AO with permuted d-columns ----
    const float inv0 = 1.0f / l0;
    const float inv1 = 1.0f / l1;
    const int pc0 = (tig < 2) ? 4 * tig : 4 * tig - 7;
    float* out0 = Og + (size_t)(q0 + r0) * HID + hoff;
    float* out1 = Og + (size_t)(q0 + r1) * HID + hoff;
#pragma unroll
    for (int nt = 0; nt < 16; nt++) {
        const int D = nt * 8;
        out0[D + pc0]     = o[nt][0] * inv0;
        out0[D + pc0 + 2] = o[nt][1] * inv0;
        out1[D + pc0]     = o[nt][2] * inv1;
        out1[D + pc0 + 2] = o[nt][3] * inv1;
    }
}

// ---------------------------------------------------------------------------
// Launch
// ---------------------------------------------------------------------------
extern "C" void kernel_launch(void* const* d_in, const int* in_sizes, int n_in,
                              void* d_out, int out_size)
{
    (void)in_sizes; (void)n_in; (void)out_size;
    const float* x    = (const float*)d_in[0];
    const float* mask = (const float*)d_in[1];
    const float* Vw[3] = { (const float*)d_in[2], (const float*)d_in[4], (const float*)d_in[6] };
    const float* Uw[3] = { (const float*)d_in[3], (const float*)d_in[5], (const float*)d_in[7] };
    const float* oW = (const float*)d_in[8];
    const float* ob = (const float*)d_in[9];
    float* out = (float*)d_out;

    void *pT, *pQKV, *pAO, *pXp, *pWp, *pUp, *pOp;
    cudaGetSymbolAddress(&pT, g_T);
    cudaGetSymbolAddress(&pQKV, g_QKV);
    cudaGetSymbolAddress(&pAO, g_AO);
    cudaGetSymbolAddress(&pXp, g_Xp);
    cudaGetSymbolAddress(&pWp, g_Wp);
    cudaGetSymbolAddress(&pUp, g_Up);
    cudaGetSymbolAddress(&pOp, g_Op);
    float* T   = (float*)pT;
    float* QKV = (float*)pQKV;
    float* AO  = (float*)pAO;
    float* Xp  = (float*)pXp;
    float* Wp  = (float*)pWp;
    float* Up  = (float*)pUp;
    float* Op  = (float*)pOp;

    cudaFuncSetAttribute(gemm_tf32_nt, cudaFuncAttributeMaxDynamicSharedMemorySize,
                         GEMM_SMEM_BYTES);
    cudaFuncSetAttribute(flash_attn_tf32, cudaFuncAttributeMaxDynamicSharedMemorySize,
                         FA_SMEM_BYTES);

    // Pre-pass: k-permute X and all weights
    {
        const int TPB = 256;
        int n8x = SEQ * HID / 8;
        permute_k8<<<(n8x + TPB - 1) / TPB, TPB>>>(x, Xp, n8x);
        int n8w = RNK * HID / 8;
        for (int i = 0; i < 3; i++) {
            permute_k8<<<(n8w + TPB - 1) / TPB, TPB>>>(Vw[i], Wp + (size_t)i * RNK * HID, n8w);
            permute_k8<<<(n8w + TPB - 1) / TPB, TPB>>>(Uw[i], Up + (size_t)i * HID * RNK, n8w);
        }
        int n8o = HID * HID / 8;
        permute_k8<<<(n8o + TPB - 1) / TPB, TPB>>>(oW, Op, n8o);
    }

    // Stage 1 (batched z=3): T_i = Xp @ Vwp_i^T  (k-permuted out)
    {
        dim3 grid(RNK / BN, SEQ / BM, 3);
        gemm_tf32_nt<<<grid, 256, GEMM_SMEM_BYTES>>>(
            Xp, Wp, T, nullptr, SEQ, RNK, HID, 1,
            0, (size_t)RNK * HID, (size_t)SEQ * RNK);
    }
    // Stage 2 (batched z=3): QKV_i = T_i @ Uwp_i^T  (d-permuted out)
    {
        dim3 grid(HID / BN, SEQ / BM, 3);
        gemm_tf32_nt<<<grid, 256, GEMM_SMEM_BYTES>>>(
            T, Up, QKV, nullptr, SEQ, HID, RNK, 1,
            (size_t)SEQ * RNK, (size_t)HID * RNK, (size_t)SEQ * HID);
    }
    // Stage 3: attention (AO d-permuted)
    {
        dim3 grid(SEQ / 128, NHEAD);
        flash_attn_tf32<<<grid, 256, FA_SMEM_BYTES>>>(
            QKV, QKV + (size_t)SEQ * HID, QKV + (size_t)2 * SEQ * HID, mask, AO);
    }
    // Stage 4: out = AO @ oWp^T + ob  (normal layout)
    {
        dim3 grid(HID / BN, SEQ / BM, 1);
        gemm_tf32_nt<<<grid, 256, GEMM_SMEM_BYTES>>>(
            AO, Op, out, ob, SEQ, HID, HID, 0, 0, 0, 0);
    }
}